// round 12
// baseline (speedup 1.0000x reference)
#include <cuda_runtime.h>
#include <cuda_fp16.h>
#include <cstdint>

#define NMAX 50000
#define NEMAX 1000000

// ---------------- scratch ----------------
__device__ __align__(16) __half g_P16[(size_t)NMAX * 128];
__device__ __align__(16) float  g_P  [(size_t)NMAX * 40 + 8];
__device__ __align__(16) float  g_H  [(size_t)NMAX * 128];
__device__ __align__(16) int    g_outdeg[NMAX + 8];
__device__ __align__(16) int    g_indeg [NMAX + 8];
__device__ int g_esrc[NEMAX];
__device__ int g_rowstart[NMAX + 8];
__device__ int g_cursor[NMAX + 8];

// ---------------- helpers ----------------
__device__ __forceinline__ uint32_t tf32_bits(float f) {
    uint32_t u;
    asm("cvt.rna.tf32.f32 %0, %1;" : "=r"(u) : "f"(f));
    return u;
}
// m16n8k8 tf32: A={a0,a1,a2,a3}, B={b0,b1}, C/D={c0..c3}
__device__ __forceinline__ void mma_tf32_k8(
    float& c0, float& c1, float& c2, float& c3,
    uint32_t a0, uint32_t a1, uint32_t a2, uint32_t a3,
    uint32_t b0, uint32_t b1)
{
    asm volatile(
        "mma.sync.aligned.m16n8k8.row.col.f32.tf32.tf32.f32 "
        "{%0,%1,%2,%3}, {%4,%5,%6,%7}, {%8,%9}, {%0,%1,%2,%3};"
        : "+f"(c0), "+f"(c1), "+f"(c2), "+f"(c3)
        : "r"(a0), "r"(a1), "r"(a2), "r"(a3), "r"(b0), "r"(b1));
}
// k-column remap within a group of 8: (k0,k4,k1,k5,k2,k6,k3,k7)
__device__ __forceinline__ int kmap(int kk) {
    return (kk & ~7) + ((kk & 3) * 2 + ((kk >> 2) & 1));
}

// ---------------- prologue ----------------
__global__ void k_degree1(const int* __restrict__ idx, int* __restrict__ deg, int nE) {
    int i = blockIdx.x * blockDim.x + threadIdx.x;
    if (i < nE) atomicAdd(&deg[idx[i]], 1);
}

__global__ void __launch_bounds__(1024)
k_scan_all(int n) {
    __shared__ int part[1024];
    int tid = threadIdx.x;
    int chunk = (n + 1023) >> 10;
    int s = tid * chunk;
    int e = min(s + chunk, n);
    int sum = 0;
    for (int i = s; i < e; ++i) sum += g_indeg[i];
    part[tid] = sum;
    __syncthreads();
    for (int off = 1; off < 1024; off <<= 1) {
        int t = 0;
        if (tid >= off) t = part[tid - off];
        __syncthreads();
        if (tid >= off) part[tid] += t;
        __syncthreads();
    }
    int run = part[tid] - sum;
    for (int i = s; i < e; ++i) {
        int d = g_indeg[i];
        g_rowstart[i] = run;
        g_cursor[i]   = run;
        run += d;
    }
    if (tid == 1023) g_rowstart[n] = run;
}

__global__ void k_scatter(const int* __restrict__ src, const int* __restrict__ dst, int nE) {
    int i = blockIdx.x * blockDim.x + threadIdx.x;
    if (i < nE) {
        int d = dst[i];
        int pos = atomicAdd(&g_cursor[d], 1);
        g_esrc[pos] = src[i];
    }
}

// ---------------- tf32 m16n8k8 GEMM: P16[r,:] = tf32(X[r,:]*onorm) @ tf32(W) --
// Tile 128 rows x 128 cols, 256 threads (8 warps), warp = 16 rows.
// Xs: [128][136] tf32 words (k pair-interleaved). Wt: [128 n][72], one K-half staged.
#define SX 136
#define SW 72
__global__ void __launch_bounds__(256)
k_gemm_tf32(const float* __restrict__ X, const float* __restrict__ W,
            __half* __restrict__ P, int n) {
    extern __shared__ uint32_t smu[];
    const int XS = 128 * SX;               // word offset of Wt

    const int tid  = threadIdx.x;
    const int lane = tid & 31;
    const int w    = tid >> 5;
    const int r0   = blockIdx.x * 128;
    const int qr   = lane >> 2;            // 0..7
    const int qc   = lane & 3;             // 0..3

    // stage Xs (tf32 bits, onorm fused, k pair-interleaved)
    for (int q = tid; q < 128 * 32; q += 256) {
        int r = q >> 5, c4 = q & 31;
        int gr = r0 + r;
        float4 v = make_float4(0.f, 0.f, 0.f, 0.f);
        if (gr < n) {
            v = ((const float4*)(X + (size_t)gr * 128))[c4];
            float s = rsqrtf(fmaxf((float)g_outdeg[gr], 1.f));
            v.x *= s; v.y *= s; v.z *= s; v.w *= s;
        }
        uint32_t* p = smu + r * SX;
        int k0 = c4 * 4;
        p[kmap(k0)]     = tf32_bits(v.x);
        p[kmap(k0 + 1)] = tf32_bits(v.y);
        p[kmap(k0 + 2)] = tf32_bits(v.z);
        p[kmap(k0 + 3)] = tf32_bits(v.w);
    }

    float acc[16][4];
#pragma unroll
    for (int t = 0; t < 16; ++t)
#pragma unroll
        for (int j = 0; j < 4; ++j) acc[t][j] = 0.f;

    const uint32_t* xr1 = smu + (16 * w + qr) * SX + 2 * qc;
    const uint32_t* xr2 = xr1 + 8 * SX;
    const uint32_t* br  = smu + XS + qr * SW + 2 * qc;

    for (int half = 0; half < 2; ++half) {
        __syncthreads();
        // stage Wt[n][kmap(kk)] = tf32(W[(64*half+kk)*128 + n])
        for (int q = tid; q < 64 * 128; q += 256) {
            int kk = q >> 7, nn = q & 127;
            smu[XS + nn * SW + kmap(kk)] = tf32_bits(W[(half * 64 + kk) * 128 + nn]);
        }
        __syncthreads();

#pragma unroll
        for (int kt = 0; kt < 8; ++kt) {
            int xoff = (half * 8 + kt) * 8;   // col base in Xs
            int woff = kt * 8;                // col base in Wt
            uint2 pA = *(const uint2*)(xr1 + xoff);   // (a0, a2)
            uint2 pB = *(const uint2*)(xr2 + xoff);   // (a1, a3)
#pragma unroll
            for (int ch = 0; ch < 2; ++ch) {
                uint2 bp[8];
#pragma unroll
                for (int j = 0; j < 8; ++j)
                    bp[j] = *(const uint2*)(br + ((ch * 8 + j) * 8) * SW + woff);
#pragma unroll
                for (int j = 0; j < 8; ++j) {
                    int nt = ch * 8 + j;
                    mma_tf32_k8(acc[nt][0], acc[nt][1], acc[nt][2], acc[nt][3],
                                pA.x, pB.x, pA.y, pB.y, bp[j].x, bp[j].y);
                }
            }
        }
    }

    // epilogue: c0,c1 -> row qr cols 8nt+2qc,+1 ; c2,c3 -> row qr+8
    {
        int r1 = r0 + 16 * w + qr;
        int r2 = r1 + 8;
        __half* prow1 = P + (size_t)r1 * 128;
        __half* prow2 = P + (size_t)r2 * 128;
        bool ok1 = (r1 < n), ok2 = (r2 < n);
#pragma unroll
        for (int nt = 0; nt < 16; ++nt) {
            int col = nt * 8 + 2 * qc;
            if (ok1) {
                __half2 h = __floats2half2_rn(acc[nt][0], acc[nt][1]);
                *(__half2*)(prow1 + col) = h;
            }
            if (ok2) {
                __half2 h = __floats2half2_rn(acc[nt][2], acc[nt][3]);
                *(__half2*)(prow2 + col) = h;
            }
        }
    }
}

// ---------------- GEMM layer 3 (128 -> 40), fp32 FFMA ----------------
template<int COLS, int NCOUT>
__global__ void __launch_bounds__(256)
k_gemm(const float* __restrict__ X, const float* __restrict__ W,
       float* __restrict__ P, int n) {
    extern __shared__ float sm[];
    float* Ws = sm;
    float* Xs = sm + 128 * COLS;

    const int tid = threadIdx.x;
    const int r0  = blockIdx.x * 64;

    for (int q = tid; q < 128 * COLS; q += 256) {
        int k = q / COLS, c = q % COLS;
        Ws[q] = (c < NCOUT) ? W[k * NCOUT + c] : 0.f;
    }
    for (int q = tid; q < 64 * 32; q += 256) {
        int r = q >> 5, c4 = q & 31;
        int gr = r0 + r;
        float4 v = make_float4(0.f, 0.f, 0.f, 0.f);
        if (gr < n) {
            v = ((const float4*)(X + (size_t)gr * 128))[c4];
            float s = rsqrtf(fmaxf((float)g_outdeg[gr], 1.f));
            v.x *= s; v.y *= s; v.z *= s; v.w *= s;
        }
        *((float4*)(Xs + r * 132 + c4 * 4)) = v;
    }
    __syncthreads();

    constexpr int CG  = COLS / 4;
    constexpr int RGC = 256 / CG;
    constexpr int RPT = 64 / RGC;
    const int cg = tid % CG;
    const int rg = tid / CG;

    float acc[RPT][4];
#pragma unroll
    for (int i = 0; i < RPT; ++i)
#pragma unroll
        for (int j = 0; j < 4; ++j) acc[i][j] = 0.f;

    const float* xbase = Xs + rg * RPT * 132;
    const float4* wc = ((const float4*)Ws) + cg;
#pragma unroll 4
    for (int k = 0; k < 128; ++k) {
        float4 b = wc[k * CG];
#pragma unroll
        for (int i = 0; i < RPT; ++i) {
            float a = xbase[i * 132 + k];
            acc[i][0] = fmaf(a, b.x, acc[i][0]);
            acc[i][1] = fmaf(a, b.y, acc[i][1]);
            acc[i][2] = fmaf(a, b.z, acc[i][2]);
            acc[i][3] = fmaf(a, b.w, acc[i][3]);
        }
    }

#pragma unroll
    for (int i = 0; i < RPT; ++i) {
        int gr = r0 + rg * RPT + i;
        if (gr >= n) continue;
        int c = cg * 4;
#pragma unroll
        for (int j = 0; j < 4; ++j)
            if (c + j < NCOUT) P[(size_t)gr * NCOUT + c + j] = acc[i][j];
    }
}

// ---------------- CSR aggregation over fp16 P, full warp per node ----------------
template<bool RELU>
__global__ void __launch_bounds__(256)
k_csr_agg128_h(const float* __restrict__ b, float* __restrict__ out, int n) {
    int w    = (blockIdx.x * blockDim.x + threadIdx.x) >> 5;
    if (w >= n) return;
    int lane = threadIdx.x & 31;
    int sub  = lane & 15;
    int grp  = lane >> 4;

    int beg = g_rowstart[w];
    int end = g_rowstart[w + 1];

    float acc[8];
#pragma unroll
    for (int j = 0; j < 8; ++j) acc[j] = 0.f;

    const uint4* P16 = (const uint4*)g_P16;

    for (int base = beg; base < end; base += 32) {
        int cnt = min(32, end - base);
        int myidx = (lane < cnt) ? g_esrc[base + lane] : 0;
        int j = 0;
        for (; j + 4 <= cnt; j += 4) {
            int sA = __shfl_sync(0xffffffffu, myidx, j + grp);
            int sB = __shfl_sync(0xffffffffu, myidx, j + 2 + grp);
            uint4 vA = P16[(size_t)sA * 16 + sub];
            uint4 vB = P16[(size_t)sB * 16 + sub];
#pragma unroll
            for (int q = 0; q < 4; ++q) {
                uint32_t uA = (&vA.x)[q];
                uint32_t uB = (&vB.x)[q];
                float2 fA = __half22float2(*(__half2*)&uA);
                float2 fB = __half22float2(*(__half2*)&uB);
                acc[2 * q]     += fA.x + fB.x;
                acc[2 * q + 1] += fA.y + fB.y;
            }
        }
        for (; j + 2 <= cnt; j += 2) {
            int s = __shfl_sync(0xffffffffu, myidx, j + grp);
            uint4 v = P16[(size_t)s * 16 + sub];
#pragma unroll
            for (int q = 0; q < 4; ++q) {
                uint32_t u = (&v.x)[q];
                float2 f = __half22float2(*(__half2*)&u);
                acc[2 * q]     += f.x;
                acc[2 * q + 1] += f.y;
            }
        }
        if (j < cnt) {
            int s = __shfl_sync(0xffffffffu, myidx, j);
            if (grp == 0) {
                uint4 v = P16[(size_t)s * 16 + sub];
#pragma unroll
                for (int q = 0; q < 4; ++q) {
                    uint32_t u = (&v.x)[q];
                    float2 f = __half22float2(*(__half2*)&u);
                    acc[2 * q]     += f.x;
                    acc[2 * q + 1] += f.y;
                }
            }
        }
    }

#pragma unroll
    for (int q = 0; q < 8; ++q)
        acc[q] += __shfl_xor_sync(0xffffffffu, acc[q], 16);

    if (grp == 0) {
        float sc = rsqrtf(fmaxf((float)g_indeg[w], 1.f));
        const float4* b4 = ((const float4*)b) + sub * 2;
        float4 bb0 = b4[0];
        float4 bb1 = b4[1];
        float4 r0, r1;
        r0.x = fmaf(acc[0], sc, bb0.x);
        r0.y = fmaf(acc[1], sc, bb0.y);
        r0.z = fmaf(acc[2], sc, bb0.z);
        r0.w = fmaf(acc[3], sc, bb0.w);
        r1.x = fmaf(acc[4], sc, bb1.x);
        r1.y = fmaf(acc[5], sc, bb1.y);
        r1.z = fmaf(acc[6], sc, bb1.z);
        r1.w = fmaf(acc[7], sc, bb1.w);
        if (RELU) {
            r0.x = fmaxf(r0.x, 0.f); r0.y = fmaxf(r0.y, 0.f);
            r0.z = fmaxf(r0.z, 0.f); r0.w = fmaxf(r0.w, 0.f);
            r1.x = fmaxf(r1.x, 0.f); r1.y = fmaxf(r1.y, 0.f);
            r1.z = fmaxf(r1.z, 0.f); r1.w = fmaxf(r1.w, 0.f);
        }
        float4* orow = ((float4*)(out + (size_t)w * 128)) + sub * 2;
        orow[0] = r0;
        orow[1] = r1;
    }
}

// ---------------- final aggregation over fp32 P (40 dims) ----------------
__global__ void __launch_bounds__(256)
k_agg40(const float* __restrict__ b, float* __restrict__ out, int n) {
    int t = blockIdx.x * blockDim.x + threadIdx.x;
    if (t >= n * 10) return;
    int node = t / 10;
    int g    = t - node * 10;

    int beg = g_rowstart[node];
    int end = g_rowstart[node + 1];

    float4 acc = make_float4(0.f, 0.f, 0.f, 0.f);
    const float4* P4 = (const float4*)g_P;
    int e = beg;
    for (; e + 2 <= end; e += 2) {
        int s0 = g_esrc[e];
        int s1 = g_esrc[e + 1];
        float4 v0 = P4[(size_t)s0 * 10 + g];
        float4 v1 = P4[(size_t)s1 * 10 + g];
        acc.x += v0.x; acc.y += v0.y; acc.z += v0.z; acc.w += v0.w;
        acc.x += v1.x; acc.y += v1.y; acc.z += v1.z; acc.w += v1.w;
    }
    if (e < end) {
        int s = g_esrc[e];
        float4 v = P4[(size_t)s * 10 + g];
        acc.x += v.x; acc.y += v.y; acc.z += v.z; acc.w += v.w;
    }

    float sc = rsqrtf(fmaxf((float)g_indeg[node], 1.f));
    float4 bb = ((const float4*)b)[g];
    float4 r;
    r.x = fmaf(acc.x, sc, bb.x);
    r.y = fmaf(acc.y, sc, bb.y);
    r.z = fmaf(acc.z, sc, bb.z);
    r.w = fmaf(acc.w, sc, bb.w);
    ((float4*)(out + (size_t)node * 40))[g] = r;
}

// ---------------- launch ----------------
extern "C" void kernel_launch(void* const* d_in, const int* in_sizes, int n_in,
                              void* d_out, int out_size) {
    const float* feat = (const float*)d_in[0];
    const float* W1   = (const float*)d_in[1];
    const float* b1   = (const float*)d_in[2];
    const float* W2   = (const float*)d_in[3];
    const float* b2   = (const float*)d_in[4];
    const float* W3   = (const float*)d_in[5];
    const float* b3   = (const float*)d_in[6];
    const int*   src  = (const int*)d_in[7];
    const int*   dst  = (const int*)d_in[8];

    const int N  = in_sizes[0] / 128;
    const int nE = in_sizes[7];
    float* out = (float*)d_out;

    __half* P16 = nullptr;
    float *P = nullptr, *H = nullptr;
    void *odeg = nullptr, *ideg = nullptr;
    cudaGetSymbolAddress((void**)&P16, g_P16);
    cudaGetSymbolAddress((void**)&P, g_P);
    cudaGetSymbolAddress((void**)&H, g_H);
    cudaGetSymbolAddress(&odeg, g_outdeg);
    cudaGetSymbolAddress(&ideg, g_indeg);

    const int SMEM_TF = (128 * SX + 128 * SW) * 4;    // 106496 B -> 2 CTAs/SM
    const int SMEM3   = (128 * 64 + 64 * 132) * 4;    // 66560 B
    cudaFuncSetAttribute(k_gemm_tf32, cudaFuncAttributeMaxDynamicSharedMemorySize, SMEM_TF);
    cudaFuncSetAttribute(k_gemm<64, 40>, cudaFuncAttributeMaxDynamicSharedMemorySize, SMEM3);

    const int T = 256;
    const int gemmBlocks  = (N + 127) / 128;
    const int gemm3Blocks = (N + 63) / 64;
    const int aggBlocks   = (N * 32 + T - 1) / T;
    const int eBlocks     = (nE + T - 1) / T;

    cudaStream_t s1;
    cudaStreamCreateWithFlags(&s1, cudaStreamNonBlocking);
    cudaEvent_t e0, e2;
    cudaEventCreateWithFlags(&e0, cudaEventDisableTiming);
    cudaEventCreateWithFlags(&e2, cudaEventDisableTiming);

    // --- fork at t=0: side stream owns dst-side (indeg + CSR build) ---
    cudaEventRecord(e0, 0);
    cudaStreamWaitEvent(s1, e0, 0);

    cudaMemsetAsync(ideg, 0, (size_t)N * 4, s1);
    k_degree1<<<eBlocks, T, 0, s1>>>(dst, (int*)ideg, nE);
    k_scan_all<<<1, 1024, 0, s1>>>(N);
    k_scatter<<<eBlocks, T, 0, s1>>>(src, dst, nE);
    cudaEventRecord(e2, s1);

    // --- main stream: src-side (outdeg) + GEMM1 ---
    cudaMemsetAsync(odeg, 0, (size_t)N * 4, 0);
    k_degree1<<<eBlocks, T>>>(src, (int*)odeg, nE);
    k_gemm_tf32<<<gemmBlocks, T, SMEM_TF>>>(feat, W1, P16, N);

    // --- join ---
    cudaStreamWaitEvent(0, e2, 0);

    // layer 1 aggregation
    k_csr_agg128_h<true><<<aggBlocks, T>>>(b1, H, N);

    // layer 2
    k_gemm_tf32<<<gemmBlocks, T, SMEM_TF>>>(H, W2, P16, N);
    k_csr_agg128_h<true><<<aggBlocks, T>>>(b2, H, N);

    // layer 3 (fp32)
    k_gemm<64, 40><<<gemm3Blocks, T, SMEM3>>>(H, W3, P, N);
    k_agg40<<<(N * 10 + T - 1) / T, T>>>(b3, out, N);

    cudaStreamCaptureStatus cap = cudaStreamCaptureStatusNone;
    cudaStreamIsCapturing(s1, &cap);
    if (cap == cudaStreamCaptureStatusNone) {
        cudaEventDestroy(e0);
        cudaEventDestroy(e2);
        cudaStreamDestroy(s1);
    }
}

// round 13
// speedup vs baseline: 1.2032x; 1.2032x over previous
#include <cuda_runtime.h>
#include <cuda_fp16.h>
#include <cstdint>

#define NMAX 50000
#define NEMAX 1000000

// ---------------- scratch ----------------
__device__ __align__(16) __half g_P16[(size_t)NMAX * 128];
__device__ __align__(16) float  g_P  [(size_t)NMAX * 40 + 8];
__device__ __align__(16) float  g_H  [(size_t)NMAX * 128];
__device__ __align__(16) int    g_outdeg[NMAX + 8];
__device__ __align__(16) int    g_indeg [NMAX + 8];
__device__ int g_esrc[NEMAX];
__device__ int g_rowstart[NMAX + 8];
__device__ int g_cursor[NMAX + 8];
__device__ int g_scan[NMAX + 8];
__device__ int g_bsum[512];

// ---------------- helpers ----------------
__device__ __forceinline__ uint32_t tf32_bits(float f) {
    uint32_t u;
    asm("cvt.rna.tf32.f32 %0, %1;" : "=r"(u) : "f"(f));
    return u;
}
__device__ __forceinline__ void mma_tf32_k4(
    float& c0, float& c1, float& c2, float& c3,
    uint32_t a0, uint32_t a1, uint32_t b0)
{
    asm volatile(
        "mma.sync.aligned.m16n8k4.row.col.f32.tf32.tf32.f32 "
        "{%0,%1,%2,%3}, {%4,%5}, {%6}, {%0,%1,%2,%3};"
        : "+f"(c0), "+f"(c1), "+f"(c2), "+f"(c3)
        : "r"(a0), "r"(a1), "r"(b0));
}

// ---------------- prologue ----------------
__global__ void k_degree1(const int* __restrict__ idx, int* __restrict__ deg, int nE) {
    int i = blockIdx.x * blockDim.x + threadIdx.x;
    if (i < nE) atomicAdd(&deg[idx[i]], 1);
}

// multi-block scan over indeg -> rowstart/cursor (R8-proven)
__global__ void k_scan1(int n) {
    __shared__ int sm[256];
    int tid = threadIdx.x;
    int i = blockIdx.x * 256 + tid;
    int v = (i < n) ? g_indeg[i] : 0;
    sm[tid] = v;
    __syncthreads();
    for (int off = 1; off < 256; off <<= 1) {
        int t = 0;
        if (tid >= off) t = sm[tid - off];
        __syncthreads();
        if (tid >= off) sm[tid] += t;
        __syncthreads();
    }
    if (i < n) g_scan[i] = sm[tid];
    if (tid == 255) g_bsum[blockIdx.x] = sm[255];
}
__global__ void k_scan2(int nb) {
    __shared__ int sm[256];
    int tid = threadIdx.x;
    int v = (tid < nb) ? g_bsum[tid] : 0;
    sm[tid] = v;
    __syncthreads();
    for (int off = 1; off < 256; off <<= 1) {
        int t = 0;
        if (tid >= off) t = sm[tid - off];
        __syncthreads();
        if (tid >= off) sm[tid] += t;
        __syncthreads();
    }
    if (tid < nb) g_bsum[tid] = sm[tid] - v;
}
__global__ void k_scan3(int n) {
    int i = blockIdx.x * blockDim.x + threadIdx.x;
    if (i < n) {
        int incl = g_scan[i] + g_bsum[i >> 8];
        int start = incl - g_indeg[i];
        g_rowstart[i] = start;
        g_cursor[i]   = start;
        if (i == n - 1) g_rowstart[n] = incl;
    }
}
__global__ void k_scatter(const int* __restrict__ src, const int* __restrict__ dst, int nE) {
    int i = blockIdx.x * blockDim.x + threadIdx.x;
    if (i < nE) {
        int d = dst[i];
        int pos = atomicAdd(&g_cursor[d], 1);
        g_esrc[pos] = src[i];
    }
}

// ---------------- tf32 tensor-core GEMM (R11-measured 44us) ----------------
// Tile 128 rows x 128 cols, 256 threads (8 warps), warp = 16 rows.
__global__ void __launch_bounds__(256)
k_gemm_tf32(const float* __restrict__ X, const float* __restrict__ W,
            __half* __restrict__ P, int n) {
    extern __shared__ uint32_t smu[];
    const int XS = 128 * 132;              // word offset of Wt

    const int tid  = threadIdx.x;
    const int lane = tid & 31;
    const int w    = tid >> 5;
    const int r0   = blockIdx.x * 128;
    const int qr   = lane >> 2;            // 0..7
    const int qc   = lane & 3;             // 0..3

    for (int q = tid; q < 128 * 32; q += 256) {
        int r = q >> 5, c4 = q & 31;
        int gr = r0 + r;
        float4 v = make_float4(0.f, 0.f, 0.f, 0.f);
        if (gr < n) {
            v = ((const float4*)(X + (size_t)gr * 128))[c4];
            float s = rsqrtf(fmaxf((float)g_outdeg[gr], 1.f));
            v.x *= s; v.y *= s; v.z *= s; v.w *= s;
        }
        uint32_t* p = smu + r * 132 + c4 * 4;
        p[0] = tf32_bits(v.x);
        p[1] = tf32_bits(v.y);
        p[2] = tf32_bits(v.z);
        p[3] = tf32_bits(v.w);
    }

    float acc[16][4];
#pragma unroll
    for (int t = 0; t < 16; ++t)
#pragma unroll
        for (int j = 0; j < 4; ++j) acc[t][j] = 0.f;

    const uint32_t* xrow = smu + (16 * w + qr) * 132 + qc;
    const uint32_t* brow = smu + XS + qr * 68 + qc;

    for (int half = 0; half < 2; ++half) {
        __syncthreads();
        for (int q = tid; q < 64 * 128; q += 256) {
            int kk = q >> 7, nn = q & 127;
            smu[XS + nn * 68 + kk] = tf32_bits(W[(half * 64 + kk) * 128 + nn]);
        }
        __syncthreads();

        const uint32_t* xh = xrow + half * 64;
#pragma unroll
        for (int kt = 0; kt < 16; ++kt) {
            uint32_t a0 = xh[kt * 4];
            uint32_t a1 = xh[8 * 132 + kt * 4];
            uint32_t b[16];
#pragma unroll
            for (int nt = 0; nt < 16; ++nt)
                b[nt] = brow[nt * 8 * 68 + kt * 4];
#pragma unroll
            for (int nt = 0; nt < 16; ++nt)
                mma_tf32_k4(acc[nt][0], acc[nt][1], acc[nt][2], acc[nt][3],
                            a0, a1, b[nt]);
        }
    }

    {
        int r1 = r0 + 16 * w + qr;
        int r2 = r1 + 8;
        __half* prow1 = P + (size_t)r1 * 128;
        __half* prow2 = P + (size_t)r2 * 128;
        bool ok1 = (r1 < n), ok2 = (r2 < n);
#pragma unroll
        for (int nt = 0; nt < 16; ++nt) {
            int col = nt * 8 + 2 * qc;
            if (ok1) {
                __half2 h = __floats2half2_rn(acc[nt][0], acc[nt][1]);
                *(__half2*)(prow1 + col) = h;
            }
            if (ok2) {
                __half2 h = __floats2half2_rn(acc[nt][2], acc[nt][3]);
                *(__half2*)(prow2 + col) = h;
            }
        }
    }
}

// ---------------- GEMM layer 3 (128 -> 40), fp32 FFMA ----------------
template<int COLS, int NCOUT>
__global__ void __launch_bounds__(256)
k_gemm(const float* __restrict__ X, const float* __restrict__ W,
       float* __restrict__ P, int n) {
    extern __shared__ float sm[];
    float* Ws = sm;
    float* Xs = sm + 128 * COLS;

    const int tid = threadIdx.x;
    const int r0  = blockIdx.x * 64;

    for (int q = tid; q < 128 * COLS; q += 256) {
        int k = q / COLS, c = q % COLS;
        Ws[q] = (c < NCOUT) ? W[k * NCOUT + c] : 0.f;
    }
    for (int q = tid; q < 64 * 32; q += 256) {
        int r = q >> 5, c4 = q & 31;
        int gr = r0 + r;
        float4 v = make_float4(0.f, 0.f, 0.f, 0.f);
        if (gr < n) {
            v = ((const float4*)(X + (size_t)gr * 128))[c4];
            float s = rsqrtf(fmaxf((float)g_outdeg[gr], 1.f));
            v.x *= s; v.y *= s; v.z *= s; v.w *= s;
        }
        *((float4*)(Xs + r * 132 + c4 * 4)) = v;
    }
    __syncthreads();

    constexpr int CG  = COLS / 4;
    constexpr int RGC = 256 / CG;
    constexpr int RPT = 64 / RGC;
    const int cg = tid % CG;
    const int rg = tid / CG;

    float acc[RPT][4];
#pragma unroll
    for (int i = 0; i < RPT; ++i)
#pragma unroll
        for (int j = 0; j < 4; ++j) acc[i][j] = 0.f;

    const float* xbase = Xs + rg * RPT * 132;
    const float4* wc = ((const float4*)Ws) + cg;
#pragma unroll 4
    for (int k = 0; k < 128; ++k) {
        float4 b = wc[k * CG];
#pragma unroll
        for (int i = 0; i < RPT; ++i) {
            float a = xbase[i * 132 + k];
            acc[i][0] = fmaf(a, b.x, acc[i][0]);
            acc[i][1] = fmaf(a, b.y, acc[i][1]);
            acc[i][2] = fmaf(a, b.z, acc[i][2]);
            acc[i][3] = fmaf(a, b.w, acc[i][3]);
        }
    }

#pragma unroll
    for (int i = 0; i < RPT; ++i) {
        int gr = r0 + rg * RPT + i;
        if (gr >= n) continue;
        int c = cg * 4;
#pragma unroll
        for (int j = 0; j < 4; ++j)
            if (c + j < NCOUT) P[(size_t)gr * NCOUT + c + j] = acc[i][j];
    }
}

// ---------------- CSR aggregation over fp16 P, full warp per node ----------------
template<bool RELU>
__global__ void __launch_bounds__(256)
k_csr_agg128_h(const float* __restrict__ b, float* __restrict__ out, int n) {
    int w    = (blockIdx.x * blockDim.x + threadIdx.x) >> 5;
    if (w >= n) return;
    int lane = threadIdx.x & 31;
    int sub  = lane & 15;
    int grp  = lane >> 4;

    int beg = g_rowstart[w];
    int end = g_rowstart[w + 1];

    float acc[8];
#pragma unroll
    for (int j = 0; j < 8; ++j) acc[j] = 0.f;

    const uint4* P16 = (const uint4*)g_P16;

    for (int base = beg; base < end; base += 32) {
        int cnt = min(32, end - base);
        int myidx = (lane < cnt) ? g_esrc[base + lane] : 0;
        int j = 0;
        for (; j + 4 <= cnt; j += 4) {
            int sA = __shfl_sync(0xffffffffu, myidx, j + grp);
            int sB = __shfl_sync(0xffffffffu, myidx, j + 2 + grp);
            uint4 vA = P16[(size_t)sA * 16 + sub];
            uint4 vB = P16[(size_t)sB * 16 + sub];
#pragma unroll
            for (int q = 0; q < 4; ++q) {
                uint32_t uA = (&vA.x)[q];
                uint32_t uB = (&vB.x)[q];
                float2 fA = __half22float2(*(__half2*)&uA);
                float2 fB = __half22float2(*(__half2*)&uB);
                acc[2 * q]     += fA.x + fB.x;
                acc[2 * q + 1] += fA.y + fB.y;
            }
        }
        for (; j + 2 <= cnt; j += 2) {
            int s = __shfl_sync(0xffffffffu, myidx, j + grp);
            uint4 v = P16[(size_t)s * 16 + sub];
#pragma unroll
            for (int q = 0; q < 4; ++q) {
                uint32_t u = (&v.x)[q];
                float2 f = __half22float2(*(__half2*)&u);
                acc[2 * q]     += f.x;
                acc[2 * q + 1] += f.y;
            }
        }
        if (j < cnt) {
            int s = __shfl_sync(0xffffffffu, myidx, j);
            if (grp == 0) {
                uint4 v = P16[(size_t)s * 16 + sub];
#pragma unroll
                for (int q = 0; q < 4; ++q) {
                    uint32_t u = (&v.x)[q];
                    float2 f = __half22float2(*(__half2*)&u);
                    acc[2 * q]     += f.x;
                    acc[2 * q + 1] += f.y;
                }
            }
        }
    }

#pragma unroll
    for (int q = 0; q < 8; ++q)
        acc[q] += __shfl_xor_sync(0xffffffffu, acc[q], 16);

    if (grp == 0) {
        float sc = rsqrtf(fmaxf((float)g_indeg[w], 1.f));
        const float4* b4 = ((const float4*)b) + sub * 2;
        float4 bb0 = b4[0];
        float4 bb1 = b4[1];
        float4 r0, r1;
        r0.x = fmaf(acc[0], sc, bb0.x);
        r0.y = fmaf(acc[1], sc, bb0.y);
        r0.z = fmaf(acc[2], sc, bb0.z);
        r0.w = fmaf(acc[3], sc, bb0.w);
        r1.x = fmaf(acc[4], sc, bb1.x);
        r1.y = fmaf(acc[5], sc, bb1.y);
        r1.z = fmaf(acc[6], sc, bb1.z);
        r1.w = fmaf(acc[7], sc, bb1.w);
        if (RELU) {
            r0.x = fmaxf(r0.x, 0.f); r0.y = fmaxf(r0.y, 0.f);
            r0.z = fmaxf(r0.z, 0.f); r0.w = fmaxf(r0.w, 0.f);
            r1.x = fmaxf(r1.x, 0.f); r1.y = fmaxf(r1.y, 0.f);
            r1.z = fmaxf(r1.z, 0.f); r1.w = fmaxf(r1.w, 0.f);
        }
        float4* orow = ((float4*)(out + (size_t)w * 128)) + sub * 2;
        orow[0] = r0;
        orow[1] = r1;
    }
}

// ---------------- final aggregation over fp32 P (40 dims) ----------------
__global__ void __launch_bounds__(256)
k_agg40(const float* __restrict__ b, float* __restrict__ out, int n) {
    int t = blockIdx.x * blockDim.x + threadIdx.x;
    if (t >= n * 10) return;
    int node = t / 10;
    int g    = t - node * 10;

    int beg = g_rowstart[node];
    int end = g_rowstart[node + 1];

    float4 acc = make_float4(0.f, 0.f, 0.f, 0.f);
    const float4* P4 = (const float4*)g_P;
    int e = beg;
    for (; e + 2 <= end; e += 2) {
        int s0 = g_esrc[e];
        int s1 = g_esrc[e + 1];
        float4 v0 = P4[(size_t)s0 * 10 + g];
        float4 v1 = P4[(size_t)s1 * 10 + g];
        acc.x += v0.x; acc.y += v0.y; acc.z += v0.z; acc.w += v0.w;
        acc.x += v1.x; acc.y += v1.y; acc.z += v1.z; acc.w += v1.w;
    }
    if (e < end) {
        int s = g_esrc[e];
        float4 v = P4[(size_t)s * 10 + g];
        acc.x += v.x; acc.y += v.y; acc.z += v.z; acc.w += v.w;
    }

    float sc = rsqrtf(fmaxf((float)g_indeg[node], 1.f));
    float4 bb = ((const float4*)b)[g];
    float4 r;
    r.x = fmaf(acc.x, sc, bb.x);
    r.y = fmaf(acc.y, sc, bb.y);
    r.z = fmaf(acc.z, sc, bb.z);
    r.w = fmaf(acc.w, sc, bb.w);
    ((float4*)(out + (size_t)node * 40))[g] = r;
}

// ---------------- launch ----------------
extern "C" void kernel_launch(void* const* d_in, const int* in_sizes, int n_in,
                              void* d_out, int out_size) {
    const float* feat = (const float*)d_in[0];
    const float* W1   = (const float*)d_in[1];
    const float* b1   = (const float*)d_in[2];
    const float* W2   = (const float*)d_in[3];
    const float* b2   = (const float*)d_in[4];
    const float* W3   = (const float*)d_in[5];
    const float* b3   = (const float*)d_in[6];
    const int*   src  = (const int*)d_in[7];
    const int*   dst  = (const int*)d_in[8];

    const int N  = in_sizes[0] / 128;
    const int nE = in_sizes[7];
    float* out = (float*)d_out;

    __half* P16 = nullptr;
    float *P = nullptr, *H = nullptr;
    void *odeg = nullptr, *ideg = nullptr;
    cudaGetSymbolAddress((void**)&P16, g_P16);
    cudaGetSymbolAddress((void**)&P, g_P);
    cudaGetSymbolAddress((void**)&H, g_H);
    cudaGetSymbolAddress(&odeg, g_outdeg);
    cudaGetSymbolAddress(&ideg, g_indeg);

    const int SMEM_TF = (128 * 132 + 128 * 68) * 4;   // 102400 B
    const int SMEM3   = (128 * 64 + 64 * 132) * 4;    // 66560 B
    cudaFuncSetAttribute(k_gemm_tf32, cudaFuncAttributeMaxDynamicSharedMemorySize, SMEM_TF);
    cudaFuncSetAttribute(k_gemm<64, 40>, cudaFuncAttributeMaxDynamicSharedMemorySize, SMEM3);

    const int T = 256;
    const int gemmBlocks  = (N + 127) / 128;
    const int gemm3Blocks = (N + 63) / 64;
    const int scanBlocks  = (N + 255) / 256;
    const int aggBlocks   = (N * 32 + T - 1) / T;
    const int eBlocks     = (nE + T - 1) / T;

    cudaStream_t s1;
    cudaStreamCreateWithFlags(&s1, cudaStreamNonBlocking);
    cudaEvent_t e0, e2;
    cudaEventCreateWithFlags(&e0, cudaEventDisableTiming);
    cudaEventCreateWithFlags(&e2, cudaEventDisableTiming);

    // --- fork at t=0: side stream owns dst-side (indeg + CSR build) ---
    cudaEventRecord(e0, 0);
    cudaStreamWaitEvent(s1, e0, 0);

    cudaMemsetAsync(ideg, 0, (size_t)N * 4, s1);
    k_degree1<<<eBlocks, T, 0, s1>>>(dst, (int*)ideg, nE);
    k_scan1<<<scanBlocks, 256, 0, s1>>>(N);
    k_scan2<<<1, 256, 0, s1>>>(scanBlocks);
    k_scan3<<<scanBlocks, 256, 0, s1>>>(N);
    k_scatter<<<eBlocks, T, 0, s1>>>(src, dst, nE);
    cudaEventRecord(e2, s1);

    // --- main stream: src-side (outdeg) + GEMM1 ---
    cudaMemsetAsync(odeg, 0, (size_t)N * 4, 0);
    k_degree1<<<eBlocks, T>>>(src, (int*)odeg, nE);
    k_gemm_tf32<<<gemmBlocks, T, SMEM_TF>>>(feat, W1, P16, N);

    // --- join ---
    cudaStreamWaitEvent(0, e2, 0);

    // layer 1 aggregation
    k_csr_agg128_h<true><<<aggBlocks, T>>>(b1, H, N);

    // layer 2
    k_gemm_tf32<<<gemmBlocks, T, SMEM_TF>>>(H, W2, P16, N);
    k_csr_agg128_h<true><<<aggBlocks, T>>>(b2, H, N);

    // layer 3 (fp32)
    k_gemm<64, 40><<<gemm3Blocks, T, SMEM3>>>(H, W3, P, N);
    k_agg40<<<(N * 10 + T - 1) / T, T>>>(b3, out, N);

    cudaStreamCaptureStatus cap = cudaStreamCaptureStatusNone;
    cudaStreamIsCapturing(s1, &cap);
    if (cap == cudaStreamCaptureStatusNone) {
        cudaEventDestroy(e0);
        cudaEventDestroy(e2);
        cudaStreamDestroy(s1);
    }
}

// round 15
// speedup vs baseline: 1.2694x; 1.0550x over previous
#include <cuda_runtime.h>
#include <cuda_fp16.h>
#include <cstdint>

#define NMAX 50000
#define NEMAX 1000000

// ---------------- scratch ----------------
__device__ __align__(16) __half g_P16[(size_t)NMAX * 128];
__device__ __align__(16) float  g_P  [(size_t)NMAX * 40 + 8];
__device__ __align__(16) float  g_H  [(size_t)NMAX * 128];
__device__ __align__(16) int    g_outdeg[NMAX + 8];
__device__ __align__(16) int    g_indeg [NMAX + 8];
__device__ int g_esrc[NEMAX];
__device__ int g_rowstart[NMAX + 8];
__device__ int g_cursor[NMAX + 8];
__device__ int g_scan[NMAX + 8];
__device__ int g_bsum[512];

// ---------------- helpers ----------------
// m16n8k16 fp16 with fp32 accumulate
__device__ __forceinline__ void mma_f16_k16(
    float& c0, float& c1, float& c2, float& c3,
    uint32_t a0, uint32_t a1, uint32_t a2, uint32_t a3,
    uint32_t b0, uint32_t b1)
{
    asm volatile(
        "mma.sync.aligned.m16n8k16.row.col.f32.f16.f16.f32 "
        "{%0,%1,%2,%3}, {%4,%5,%6,%7}, {%8,%9}, {%0,%1,%2,%3};"
        : "+f"(c0), "+f"(c1), "+f"(c2), "+f"(c3)
        : "r"(a0), "r"(a1), "r"(a2), "r"(a3), "r"(b0), "r"(b1));
}
// slot (in half units, within a 16-k group) of the k-pair p = (k>>1)&7:
// pairs ordered (0,4,1,5,2,6,3,7) so (p, p+4) are adjacent -> LDS.64 fragments
__device__ __forceinline__ int pslot(int p) { return ((p & 3) * 2 + (p >> 2)) * 2; }

// ---------------- prologue ----------------
__global__ void k_degree1(const int* __restrict__ idx, int* __restrict__ deg, int nE) {
    int i = blockIdx.x * blockDim.x + threadIdx.x;
    if (i < nE) atomicAdd(&deg[idx[i]], 1);
}

__global__ void k_scan1(int n) {
    __shared__ int sm[256];
    int tid = threadIdx.x;
    int i = blockIdx.x * 256 + tid;
    int v = (i < n) ? g_indeg[i] : 0;
    sm[tid] = v;
    __syncthreads();
    for (int off = 1; off < 256; off <<= 1) {
        int t = 0;
        if (tid >= off) t = sm[tid - off];
        __syncthreads();
        if (tid >= off) sm[tid] += t;
        __syncthreads();
    }
    if (i < n) g_scan[i] = sm[tid];
    if (tid == 255) g_bsum[blockIdx.x] = sm[255];
}
__global__ void k_scan2(int nb) {
    __shared__ int sm[256];
    int tid = threadIdx.x;
    int v = (tid < nb) ? g_bsum[tid] : 0;
    sm[tid] = v;
    __syncthreads();
    for (int off = 1; off < 256; off <<= 1) {
        int t = 0;
        if (tid >= off) t = sm[tid - off];
        __syncthreads();
        if (tid >= off) sm[tid] += t;
        __syncthreads();
    }
    if (tid < nb) g_bsum[tid] = sm[tid] - v;
}
__global__ void k_scan3(int n) {
    int i = blockIdx.x * blockDim.x + threadIdx.x;
    if (i < n) {
        int incl = g_scan[i] + g_bsum[i >> 8];
        int start = incl - g_indeg[i];
        g_rowstart[i] = start;
        g_cursor[i]   = start;
        if (i == n - 1) g_rowstart[n] = incl;
    }
}
__global__ void k_scatter(const int* __restrict__ src, const int* __restrict__ dst, int nE) {
    int i = blockIdx.x * blockDim.x + threadIdx.x;
    if (i < nE) {
        int d = dst[i];
        int pos = atomicAdd(&g_cursor[d], 1);
        g_esrc[pos] = src[i];
    }
}

// ---------------- fp16 m16n8k16 GEMM: P16[r,:] = h(X[r,:]*onorm) @ h(W) ------
// Tile 128 rows x 128 cols, 256 threads (8 warps), warp = 16 rows x 128 cols.
// Xs: [128][144] halfs (pair-interleaved k). Wt: [128 n][136] halfs (full K, W^T).
#define SXH 144
#define SWH 136
__global__ void __launch_bounds__(256)
k_gemm_h16(const float* __restrict__ X, const float* __restrict__ W,
           __half* __restrict__ P, int n) {
    extern __shared__ __half smh[];
    __half* Xs = smh;                     // 128*144 halfs
    __half* Wt = smh + 128 * SXH;         // 128*136 halfs

    const int tid  = threadIdx.x;
    const int lane = tid & 31;
    const int w    = tid >> 5;
    const int r0   = blockIdx.x * 128;
    const int qr   = lane >> 2;           // 0..7
    const int qc   = lane & 3;            // 0..3

    // stage Xs (fp16, onorm fused, pair-interleaved k)
    for (int q = tid; q < 128 * 32; q += 256) {
        int r = q >> 5, c4 = q & 31;
        int gr = r0 + r;
        float4 v = make_float4(0.f, 0.f, 0.f, 0.f);
        if (gr < n) {
            v = ((const float4*)(X + (size_t)gr * 128))[c4];
            float s = rsqrtf(fmaxf((float)g_outdeg[gr], 1.f));
            v.x *= s; v.y *= s; v.z *= s; v.w *= s;
        }
        int k0 = c4 * 4;
        int base = k0 & ~15;
        int p0 = (k0 >> 1) & 7;           // in {0,2,4,6}
        __half* row = Xs + r * SXH + base;
        *(__half2*)(row + pslot(p0))     = __floats2half2_rn(v.x, v.y);
        *(__half2*)(row + pslot(p0 + 1)) = __floats2half2_rn(v.z, v.w);
    }

    // stage Wt[n][k] = h(W[k*128+n]), full K at once
    for (int q = tid; q < 128 * 128; q += 256) {
        int kk = q >> 7, nn = q & 127;
        int base = kk & ~15;
        int s = base + pslot((kk >> 1) & 7) + (kk & 1);
        Wt[nn * SWH + s] = __float2half_rn(W[kk * 128 + nn]);
    }
    __syncthreads();

    float acc[16][4];
#pragma unroll
    for (int t = 0; t < 16; ++t)
#pragma unroll
        for (int j = 0; j < 4; ++j) acc[t][j] = 0.f;

    const __half* xr1 = Xs + (16 * w + qr) * SXH + 4 * qc;
    const __half* xr2 = xr1 + 8 * SXH;
    const __half* br  = Wt + qr * SWH + 4 * qc;

#pragma unroll
    for (int kt = 0; kt < 8; ++kt) {
        int off = kt * 16;
        uint2 pA1 = *(const uint2*)(xr1 + off);   // (a0, a2): row qr,  k-pairs (qc, qc+4)
        uint2 pA2 = *(const uint2*)(xr2 + off);   // (a1, a3): row qr+8
#pragma unroll
        for (int ch = 0; ch < 2; ++ch) {
            uint2 bp[8];
#pragma unroll
            for (int j = 0; j < 8; ++j)
                bp[j] = *(const uint2*)(br + (ch * 8 + j) * 8 * SWH + off);
#pragma unroll
            for (int j = 0; j < 8; ++j) {
                int nt = ch * 8 + j;
                mma_f16_k16(acc[nt][0], acc[nt][1], acc[nt][2], acc[nt][3],
                            pA1.x, pA2.x, pA1.y, pA2.y, bp[j].x, bp[j].y);
            }
        }
    }

    // epilogue: c0,c1 -> row qr cols 8nt+2qc,+1 ; c2,c3 -> row qr+8
    {
        int r1 = r0 + 16 * w + qr;
        int r2 = r1 + 8;
        __half* prow1 = P + (size_t)r1 * 128;
        __half* prow2 = P + (size_t)r2 * 128;
        bool ok1 = (r1 < n), ok2 = (r2 < n);
#pragma unroll
        for (int nt = 0; nt < 16; ++nt) {
            int col = nt * 8 + 2 * qc;
            if (ok1) {
                __half2 h = __floats2half2_rn(acc[nt][0], acc[nt][1]);
                *(__half2*)(prow1 + col) = h;
            }
            if (ok2) {
                __half2 h = __floats2half2_rn(acc[nt][2], acc[nt][3]);
                *(__half2*)(prow2 + col) = h;
            }
        }
    }
}

// ---------------- GEMM layer 3 (128 -> 40), fp32 FFMA ----------------
template<int COLS, int NCOUT>
__global__ void __launch_bounds__(256)
k_gemm(const float* __restrict__ X, const float* __restrict__ W,
       float* __restrict__ P, int n) {
    extern __shared__ float sm[];
    float* Ws = sm;
    float* Xs = sm + 128 * COLS;

    const int tid = threadIdx.x;
    const int r0  = blockIdx.x * 64;

    for (int q = tid; q < 128 * COLS; q += 256) {
        int k = q / COLS, c = q % COLS;
        Ws[q] = (c < NCOUT) ? W[k * NCOUT + c] : 0.f;
    }
    for (int q = tid; q < 64 * 32; q += 256) {
        int r = q >> 5, c4 = q & 31;
        int gr = r0 + r;
        float4 v = make_float4(0.f, 0.f, 0.f, 0.f);
        if (gr < n) {
            v = ((const float4*)(X + (size_t)gr * 128))[c4];
            float s = rsqrtf(fmaxf((float)g_outdeg[gr], 1.f));
            v.x *= s; v.y *= s; v.z *= s; v.w *= s;
        }
        *((float4*)(Xs + r * 132 + c4 * 4)) = v;
    }
    __syncthreads();

    constexpr int CG  = COLS / 4;
    constexpr int RGC = 256 / CG;
    constexpr int RPT = 64 / RGC;
    const int cg = tid % CG;
    const int rg = tid / CG;

    float acc[RPT][4];
#pragma unroll
    for (int i = 0; i < RPT; ++i)
#pragma unroll
        for (int j = 0; j < 4; ++j) acc[i][j] = 0.f;

    const float* xbase = Xs + rg * RPT * 132;
    const float4* wc = ((const float4*)Ws) + cg;
#pragma unroll 4
    for (int k = 0; k < 128; ++k) {
        float4 b = wc[k * CG];
#pragma unroll
        for (int i = 0; i < RPT; ++i) {
            float a = xbase[i * 132 + k];
            acc[i][0] = fmaf(a, b.x, acc[i][0]);
            acc[i][1] = fmaf(a, b.y, acc[i][1]);
            acc[i][2] = fmaf(a, b.z, acc[i][2]);
            acc[i][3] = fmaf(a, b.w, acc[i][3]);
        }
    }

#pragma unroll
    for (int i = 0; i < RPT; ++i) {
        int gr = r0 + rg * RPT + i;
        if (gr >= n) continue;
        int c = cg * 4;
#pragma unroll
        for (int j = 0; j < 4; ++j)
            if (c + j < NCOUT) P[(size_t)gr * NCOUT + c + j] = acc[i][j];
    }
}

// ---------------- CSR aggregation over fp16 P, full warp per node ----------------
template<bool RELU>
__global__ void __launch_bounds__(256)
k_csr_agg128_h(const float* __restrict__ b, float* __restrict__ out, int n) {
    int w    = (blockIdx.x * blockDim.x + threadIdx.x) >> 5;
    if (w >= n) return;
    int lane = threadIdx.x & 31;
    int sub  = lane & 15;
    int grp  = lane >> 4;

    int beg = g_rowstart[w];
    int end = g_rowstart[w + 1];

    float acc[8];
#pragma unroll
    for (int j = 0; j < 8; ++j) acc[j] = 0.f;

    const uint4* P16 = (const uint4*)g_P16;

    for (int base = beg; base < end; base += 32) {
        int cnt = min(32, end - base);
        int myidx = (lane < cnt) ? g_esrc[base + lane] : 0;
        int j = 0;
        for (; j + 4 <= cnt; j += 4) {
            int sA = __shfl_sync(0xffffffffu, myidx, j + grp);
            int sB = __shfl_sync(0xffffffffu, myidx, j + 2 + grp);
            uint4 vA = P16[(size_t)sA * 16 + sub];
            uint4 vB = P16[(size_t)sB * 16 + sub];
#pragma unroll
            for (int q = 0; q < 4; ++q) {
                uint32_t uA = (&vA.x)[q];
                uint32_t uB = (&vB.x)[q];
                float2 fA = __half22float2(*(__half2*)&uA);
                float2 fB = __half22float2(*(__half2*)&uB);
                acc[2 * q]     += fA.x + fB.x;
                acc[2 * q + 1] += fA.y + fB.y;
            }
        }
        for (; j + 2 <= cnt; j += 2) {
            int s = __shfl_sync(0xffffffffu, myidx, j + grp);
            uint4 v = P16[(size_t)s * 16 + sub];
#pragma unroll
            for (int q = 0; q < 4; ++q) {
                uint32_t u = (&v.x)[q];
                float2 f = __half22float2(*(__half2*)&u);
                acc[2 * q]     += f.x;
                acc[2 * q + 1] += f.y;
            }
        }
        if (j < cnt) {
            int s = __shfl_sync(0xffffffffu, myidx, j);
            if (grp == 0) {
                uint4 v = P16[(size_t)s * 16 + sub];
#pragma unroll
                for (int q = 0; q < 4; ++q) {
                    uint32_t u = (&v.x)[q];
                    float2 f = __half22float2(*(__half2*)&u);
                    acc[2 * q]     += f.x;
                    acc[2 * q + 1] += f.y;
                }
            }
        }
    }

#pragma unroll
    for (int q = 0; q < 8; ++q)
        acc[q] += __shfl_xor_sync(0xffffffffu, acc[q], 16);

    if (grp == 0) {
        float sc = rsqrtf(fmaxf((float)g_indeg[w], 1.f));
        const float4* b4 = ((const float4*)b) + sub * 2;
        float4 bb0 = b4[0];
        float4 bb1 = b4[1];
        float4 r0, r1;
        r0.x = fmaf(acc[0], sc, bb0.x);
        r0.y = fmaf(acc[1], sc, bb0.y);
        r0.z = fmaf(acc[2], sc, bb0.z);
        r0.w = fmaf(acc[3], sc, bb0.w);
        r1.x = fmaf(acc[4], sc, bb1.x);
        r1.y = fmaf(acc[5], sc, bb1.y);
        r1.z = fmaf(acc[6], sc, bb1.z);
        r1.w = fmaf(acc[7], sc, bb1.w);
        if (RELU) {
            r0.x = fmaxf(r0.x, 0.f); r0.y = fmaxf(r0.y, 0.f);
            r0.z = fmaxf(r0.z, 0.f); r0.w = fmaxf(r0.w, 0.f);
            r1.x = fmaxf(r1.x, 0.f); r1.y = fmaxf(r1.y, 0.f);
            r1.z = fmaxf(r1.z, 0.f); r1.w = fmaxf(r1.w, 0.f);
        }
        float4* orow = ((float4*)(out + (size_t)w * 128)) + sub * 2;
        orow[0] = r0;
        orow[1] = r1;
    }
}

// ---------------- final aggregation over fp32 P (40 dims) ----------------
__global__ void __launch_bounds__(256)
k_agg40(const float* __restrict__ b, float* __restrict__ out, int n) {
    int t = blockIdx.x * blockDim.x + threadIdx.x;
    if (t >= n * 10) return;
    int node = t / 10;
    int g    = t - node * 10;

    int beg = g_rowstart[node];
    int end = g_rowstart[node + 1];

    float4 acc = make_float4(0.f, 0.f, 0.f, 0.f);
    const float4* P4 = (const float4*)g_P;
    int e = beg;
    for (; e + 2 <= end; e += 2) {
        int s0 = g_esrc[e];
        int s1 = g_esrc[e + 1];
        float4 v0 = P4[(size_t)s0 * 10 + g];
        float4 v1 = P4[(size_t)s1 * 10 + g];
        acc.x += v0.x; acc.y += v0.y; acc.z += v0.z; acc.w += v0.w;
        acc.x += v1.x; acc.y += v1.y; acc.z += v1.z; acc.w += v1.w;
    }
    if (e < end) {
        int s = g_esrc[e];
        float4 v = P4[(size_t)s * 10 + g];
        acc.x += v.x; acc.y += v.y; acc.z += v.z; acc.w += v.w;
    }

    float sc = rsqrtf(fmaxf((float)g_indeg[node], 1.f));
    float4 bb = ((const float4*)b)[g];
    float4 r;
    r.x = fmaf(acc.x, sc, bb.x);
    r.y = fmaf(acc.y, sc, bb.y);
    r.z = fmaf(acc.z, sc, bb.z);
    r.w = fmaf(acc.w, sc, bb.w);
    ((float4*)(out + (size_t)node * 40))[g] = r;
}

// ---------------- launch ----------------
extern "C" void kernel_launch(void* const* d_in, const int* in_sizes, int n_in,
                              void* d_out, int out_size) {
    const float* feat = (const float*)d_in[0];
    const float* W1   = (const float*)d_in[1];
    const float* b1   = (const float*)d_in[2];
    const float* W2   = (const float*)d_in[3];
    const float* b2   = (const float*)d_in[4];
    const float* W3   = (const float*)d_in[5];
    const float* b3   = (const float*)d_in[6];
    const int*   src  = (const int*)d_in[7];
    const int*   dst  = (const int*)d_in[8];

    const int N  = in_sizes[0] / 128;
    const int nE = in_sizes[7];
    float* out = (float*)d_out;

    __half* P16 = nullptr;
    float *P = nullptr, *H = nullptr;
    void *odeg = nullptr, *ideg = nullptr;
    cudaGetSymbolAddress((void**)&P16, g_P16);
    cudaGetSymbolAddress((void**)&P, g_P);
    cudaGetSymbolAddress((void**)&H, g_H);
    cudaGetSymbolAddress(&odeg, g_outdeg);
    cudaGetSymbolAddress(&ideg, g_indeg);

    const int SMEM_H16 = (128 * SXH + 128 * SWH) * 2;  // 71680 B
    const int SMEM3    = (128 * 64 + 64 * 132) * 4;    // 66560 B
    cudaFuncSetAttribute(k_gemm_h16, cudaFuncAttributeMaxDynamicSharedMemorySize, SMEM_H16);
    cudaFuncSetAttribute(k_gemm<64, 40>, cudaFuncAttributeMaxDynamicSharedMemorySize, SMEM3);

    const int T = 256;
    const int gemmBlocks  = (N + 127) / 128;
    const int gemm3Blocks = (N + 63) / 64;
    const int scanBlocks  = (N + 255) / 256;
    const int aggBlocks   = (N * 32 + T - 1) / T;
    const int eBlocks     = (nE + T - 1) / T;

    cudaStream_t s1;
    cudaStreamCreateWithFlags(&s1, cudaStreamNonBlocking);
    cudaEvent_t e0, e2;
    cudaEventCreateWithFlags(&e0, cudaEventDisableTiming);
    cudaEventCreateWithFlags(&e2, cudaEventDisableTiming);

    // --- fork at t=0: side stream owns dst-side (indeg + CSR build) ---
    cudaEventRecord(e0, 0);
    cudaStreamWaitEvent(s1, e0, 0);

    cudaMemsetAsync(ideg, 0, (size_t)N * 4, s1);
    k_degree1<<<eBlocks, T, 0, s1>>>(dst, (int*)ideg, nE);
    k_scan1<<<scanBlocks, 256, 0, s1>>>(N);
    k_scan2<<<1, 256, 0, s1>>>(scanBlocks);
    k_scan3<<<scanBlocks, 256, 0, s1>>>(N);
    k_scatter<<<eBlocks, T, 0, s1>>>(src, dst, nE);
    cudaEventRecord(e2, s1);

    // --- main stream: src-side (outdeg) + GEMM1 ---
    cudaMemsetAsync(odeg, 0, (size_t)N * 4, 0);
    k_degree1<<<eBlocks, T>>>(src, (int*)odeg, nE);
    k_gemm_h16<<<gemmBlocks, T, SMEM_H16>>>(feat, W1, P16, N);

    // --- join ---
    cudaStreamWaitEvent(0, e2, 0);

    // layer 1 aggregation
    k_csr_agg128_h<true><<<aggBlocks, T>>>(b1, H, N);

    // layer 2
    k_gemm_h16<<<gemmBlocks, T, SMEM_H16>>>(H, W2, P16, N);
    k_csr_agg128_h<true><<<aggBlocks, T>>>(b2, H, N);

    // layer 3 (fp32)
    k_gemm<64, 40><<<gemm3Blocks, T, SMEM3>>>(H, W3, P, N);
    k_agg40<<<(N * 10 + T - 1) / T, T>>>(b3, out, N);

    cudaStreamCaptureStatus cap = cudaStreamCaptureStatusNone;
    cudaStreamIsCapturing(s1, &cap);
    if (cap == cudaStreamCaptureStatusNone) {
        cudaEventDestroy(e0);
        cudaEventDestroy(e2);
        cudaStreamDestroy(s1);
    }
}

// round 16
// speedup vs baseline: 1.4120x; 1.1124x over previous
#include <cuda_runtime.h>
#include <cuda_fp16.h>
#include <cstdint>

#define NMAX 50000
#define NEMAX 1000000

// ---------------- scratch ----------------
__device__ __align__(16) __half g_P16[(size_t)NMAX * 128];
__device__ __align__(16) float  g_P  [(size_t)NMAX * 40 + 8];
__device__ __align__(16) float  g_H  [(size_t)NMAX * 128];
__device__ __align__(16) int    g_outdeg[NMAX + 8];
__device__ __align__(16) int    g_indeg [NMAX + 8];
__device__ int g_esrc[NEMAX];
__device__ int g_rowstart[NMAX + 8];
__device__ int g_cursor[NMAX + 8];
__device__ int g_scan[NMAX + 8];
__device__ int g_bsum[512];

// ---------------- helpers ----------------
// m16n8k16 fp16 with fp32 accumulate
__device__ __forceinline__ void mma_f16_k16(
    float& c0, float& c1, float& c2, float& c3,
    uint32_t a0, uint32_t a1, uint32_t a2, uint32_t a3,
    uint32_t b0, uint32_t b1)
{
    asm volatile(
        "mma.sync.aligned.m16n8k16.row.col.f32.f16.f16.f32 "
        "{%0,%1,%2,%3}, {%4,%5,%6,%7}, {%8,%9}, {%0,%1,%2,%3};"
        : "+f"(c0), "+f"(c1), "+f"(c2), "+f"(c3)
        : "r"(a0), "r"(a1), "r"(a2), "r"(a3), "r"(b0), "r"(b1));
}
// slot (in half units, within a 16-k group) of the k-pair p = (k>>1)&7:
// pairs ordered (0,4,1,5,2,6,3,7) so (p, p+4) are adjacent -> LDS.64 fragments
__device__ __forceinline__ int pslot(int p) { return ((p & 3) * 2 + (p >> 2)) * 2; }

// ---------------- prologue ----------------
__global__ void k_degree1(const int* __restrict__ idx, int* __restrict__ deg, int nE) {
    int i = blockIdx.x * blockDim.x + threadIdx.x;
    if (i < nE) atomicAdd(&deg[idx[i]], 1);
}

__global__ void k_scan1(int n) {
    __shared__ int sm[256];
    int tid = threadIdx.x;
    int i = blockIdx.x * 256 + tid;
    int v = (i < n) ? g_indeg[i] : 0;
    sm[tid] = v;
    __syncthreads();
    for (int off = 1; off < 256; off <<= 1) {
        int t = 0;
        if (tid >= off) t = sm[tid - off];
        __syncthreads();
        if (tid >= off) sm[tid] += t;
        __syncthreads();
    }
    if (i < n) g_scan[i] = sm[tid];
    if (tid == 255) g_bsum[blockIdx.x] = sm[255];
}
__global__ void k_scan2(int nb) {
    __shared__ int sm[256];
    int tid = threadIdx.x;
    int v = (tid < nb) ? g_bsum[tid] : 0;
    sm[tid] = v;
    __syncthreads();
    for (int off = 1; off < 256; off <<= 1) {
        int t = 0;
        if (tid >= off) t = sm[tid - off];
        __syncthreads();
        if (tid >= off) sm[tid] += t;
        __syncthreads();
    }
    if (tid < nb) g_bsum[tid] = sm[tid] - v;
}
__global__ void k_scan3(int n) {
    int i = blockIdx.x * blockDim.x + threadIdx.x;
    if (i < n) {
        int incl = g_scan[i] + g_bsum[i >> 8];
        int start = incl - g_indeg[i];
        g_rowstart[i] = start;
        g_cursor[i]   = start;
        if (i == n - 1) g_rowstart[n] = incl;
    }
}
__global__ void k_scatter(const int* __restrict__ src, const int* __restrict__ dst, int nE) {
    int i = blockIdx.x * blockDim.x + threadIdx.x;
    if (i < nE) {
        int d = dst[i];
        int pos = atomicAdd(&g_cursor[d], 1);
        g_esrc[pos] = src[i];
    }
}

// ---------------- fp16 m16n8k16 GEMM core (templated on NCOLS, output kind) ----
// Tile 128 rows x NCOLS cols, 256 threads (8 warps), warp = 16 rows.
// Xs: [128][144] halfs (pair-interleaved k). Wt: [NCOLS n][136] halfs (full K, W^T).
#define SXH 144
#define SWH 136

// stage Xs from fp32 input with onorm fused
__device__ __forceinline__ void stage_xs(
    __half* Xs, const float* __restrict__ X, int r0, int n, int tid)
{
    for (int q = tid; q < 128 * 32; q += 256) {
        int r = q >> 5, c4 = q & 31;
        int gr = r0 + r;
        float4 v = make_float4(0.f, 0.f, 0.f, 0.f);
        if (gr < n) {
            v = ((const float4*)(X + (size_t)gr * 128))[c4];
            float s = rsqrtf(fmaxf((float)g_outdeg[gr], 1.f));
            v.x *= s; v.y *= s; v.z *= s; v.w *= s;
        }
        int k0 = c4 * 4;
        int base = k0 & ~15;
        int p0 = (k0 >> 1) & 7;
        __half* row = Xs + r * SXH + base;
        *(__half2*)(row + pslot(p0))     = __floats2half2_rn(v.x, v.y);
        *(__half2*)(row + pslot(p0 + 1)) = __floats2half2_rn(v.z, v.w);
    }
}

// ---------------- layer 1/2 GEMM: 128 cols, fp16 output ----------------
__global__ void __launch_bounds__(256)
k_gemm_h16(const float* __restrict__ X, const float* __restrict__ W,
           __half* __restrict__ P, int n) {
    extern __shared__ __half smh[];
    __half* Xs = smh;                     // 128*144 halfs
    __half* Wt = smh + 128 * SXH;         // 128*136 halfs

    const int tid  = threadIdx.x;
    const int lane = tid & 31;
    const int w    = tid >> 5;
    const int r0   = blockIdx.x * 128;
    const int qr   = lane >> 2;
    const int qc   = lane & 3;

    stage_xs(Xs, X, r0, n, tid);

    for (int q = tid; q < 128 * 128; q += 256) {
        int kk = q >> 7, nn = q & 127;
        int base = kk & ~15;
        int s = base + pslot((kk >> 1) & 7) + (kk & 1);
        Wt[nn * SWH + s] = __float2half_rn(W[kk * 128 + nn]);
    }
    __syncthreads();

    float acc[16][4];
#pragma unroll
    for (int t = 0; t < 16; ++t)
#pragma unroll
        for (int j = 0; j < 4; ++j) acc[t][j] = 0.f;

    const __half* xr1 = Xs + (16 * w + qr) * SXH + 4 * qc;
    const __half* xr2 = xr1 + 8 * SXH;
    const __half* br  = Wt + qr * SWH + 4 * qc;

#pragma unroll
    for (int kt = 0; kt < 8; ++kt) {
        int off = kt * 16;
        uint2 pA1 = *(const uint2*)(xr1 + off);
        uint2 pA2 = *(const uint2*)(xr2 + off);
#pragma unroll
        for (int ch = 0; ch < 2; ++ch) {
            uint2 bp[8];
#pragma unroll
            for (int j = 0; j < 8; ++j)
                bp[j] = *(const uint2*)(br + (ch * 8 + j) * 8 * SWH + off);
#pragma unroll
            for (int j = 0; j < 8; ++j) {
                int nt = ch * 8 + j;
                mma_f16_k16(acc[nt][0], acc[nt][1], acc[nt][2], acc[nt][3],
                            pA1.x, pA2.x, pA1.y, pA2.y, bp[j].x, bp[j].y);
            }
        }
    }

    {
        int r1 = r0 + 16 * w + qr;
        int r2 = r1 + 8;
        __half* prow1 = P + (size_t)r1 * 128;
        __half* prow2 = P + (size_t)r2 * 128;
        bool ok1 = (r1 < n), ok2 = (r2 < n);
#pragma unroll
        for (int nt = 0; nt < 16; ++nt) {
            int col = nt * 8 + 2 * qc;
            if (ok1) {
                __half2 h = __floats2half2_rn(acc[nt][0], acc[nt][1]);
                *(__half2*)(prow1 + col) = h;
            }
            if (ok2) {
                __half2 h = __floats2half2_rn(acc[nt][2], acc[nt][3]);
                *(__half2*)(prow2 + col) = h;
            }
        }
    }
}

// ---------------- layer 3 GEMM: 40 cols, fp32 output ----------------
__global__ void __launch_bounds__(256)
k_gemm_h16_40(const float* __restrict__ X, const float* __restrict__ W,
              float* __restrict__ P, int n) {
    extern __shared__ __half smh[];
    __half* Xs = smh;                     // 128*144 halfs
    __half* Wt = smh + 128 * SXH;         // 40*136 halfs

    const int tid  = threadIdx.x;
    const int lane = tid & 31;
    const int w    = tid >> 5;
    const int r0   = blockIdx.x * 128;
    const int qr   = lane >> 2;
    const int qc   = lane & 3;

    stage_xs(Xs, X, r0, n, tid);

    for (int q = tid; q < 128 * 40; q += 256) {
        int kk = q / 40, nn = q % 40;
        int base = kk & ~15;
        int s = base + pslot((kk >> 1) & 7) + (kk & 1);
        Wt[nn * SWH + s] = __float2half_rn(W[kk * 40 + nn]);
    }
    __syncthreads();

    float acc[5][4];
#pragma unroll
    for (int t = 0; t < 5; ++t)
#pragma unroll
        for (int j = 0; j < 4; ++j) acc[t][j] = 0.f;

    const __half* xr1 = Xs + (16 * w + qr) * SXH + 4 * qc;
    const __half* xr2 = xr1 + 8 * SXH;
    const __half* br  = Wt + qr * SWH + 4 * qc;

#pragma unroll
    for (int kt = 0; kt < 8; ++kt) {
        int off = kt * 16;
        uint2 pA1 = *(const uint2*)(xr1 + off);
        uint2 pA2 = *(const uint2*)(xr2 + off);
        uint2 bp[5];
#pragma unroll
        for (int j = 0; j < 5; ++j)
            bp[j] = *(const uint2*)(br + j * 8 * SWH + off);
#pragma unroll
        for (int j = 0; j < 5; ++j)
            mma_f16_k16(acc[j][0], acc[j][1], acc[j][2], acc[j][3],
                        pA1.x, pA2.x, pA1.y, pA2.y, bp[j].x, bp[j].y);
    }

    {
        int r1 = r0 + 16 * w + qr;
        int r2 = r1 + 8;
        bool ok1 = (r1 < n), ok2 = (r2 < n);
#pragma unroll
        for (int nt = 0; nt < 5; ++nt) {
            int col = nt * 8 + 2 * qc;
            if (ok1)
                *(float2*)(P + (size_t)r1 * 40 + col) = make_float2(acc[nt][0], acc[nt][1]);
            if (ok2)
                *(float2*)(P + (size_t)r2 * 40 + col) = make_float2(acc[nt][2], acc[nt][3]);
        }
    }
}

// ---------------- CSR aggregation over fp16 P, full warp per node ----------------
template<bool RELU>
__global__ void __launch_bounds__(256)
k_csr_agg128_h(const float* __restrict__ b, float* __restrict__ out, int n) {
    int w    = (blockIdx.x * blockDim.x + threadIdx.x) >> 5;
    if (w >= n) return;
    int lane = threadIdx.x & 31;
    int sub  = lane & 15;
    int grp  = lane >> 4;

    int beg = g_rowstart[w];
    int end = g_rowstart[w + 1];

    float acc[8];
#pragma unroll
    for (int j = 0; j < 8; ++j) acc[j] = 0.f;

    const uint4* P16 = (const uint4*)g_P16;

    for (int base = beg; base < end; base += 32) {
        int cnt = min(32, end - base);
        int myidx = (lane < cnt) ? g_esrc[base + lane] : 0;
        int j = 0;
        for (; j + 4 <= cnt; j += 4) {
            int sA = __shfl_sync(0xffffffffu, myidx, j + grp);
            int sB = __shfl_sync(0xffffffffu, myidx, j + 2 + grp);
            uint4 vA = P16[(size_t)sA * 16 + sub];
            uint4 vB = P16[(size_t)sB * 16 + sub];
#pragma unroll
            for (int q = 0; q < 4; ++q) {
                uint32_t uA = (&vA.x)[q];
                uint32_t uB = (&vB.x)[q];
                float2 fA = __half22float2(*(__half2*)&uA);
                float2 fB = __half22float2(*(__half2*)&uB);
                acc[2 * q]     += fA.x + fB.x;
                acc[2 * q + 1] += fA.y + fB.y;
            }
        }
        for (; j + 2 <= cnt; j += 2) {
            int s = __shfl_sync(0xffffffffu, myidx, j + grp);
            uint4 v = P16[(size_t)s * 16 + sub];
#pragma unroll
            for (int q = 0; q < 4; ++q) {
                uint32_t u = (&v.x)[q];
                float2 f = __half22float2(*(__half2*)&u);
                acc[2 * q]     += f.x;
                acc[2 * q + 1] += f.y;
            }
        }
        if (j < cnt) {
            int s = __shfl_sync(0xffffffffu, myidx, j);
            if (grp == 0) {
                uint4 v = P16[(size_t)s * 16 + sub];
#pragma unroll
                for (int q = 0; q < 4; ++q) {
                    uint32_t u = (&v.x)[q];
                    float2 f = __half22float2(*(__half2*)&u);
                    acc[2 * q]     += f.x;
                    acc[2 * q + 1] += f.y;
                }
            }
        }
    }

#pragma unroll
    for (int q = 0; q < 8; ++q)
        acc[q] += __shfl_xor_sync(0xffffffffu, acc[q], 16);

    if (grp == 0) {
        float sc = rsqrtf(fmaxf((float)g_indeg[w], 1.f));
        const float4* b4 = ((const float4*)b) + sub * 2;
        float4 bb0 = b4[0];
        float4 bb1 = b4[1];
        float4 r0, r1;
        r0.x = fmaf(acc[0], sc, bb0.x);
        r0.y = fmaf(acc[1], sc, bb0.y);
        r0.z = fmaf(acc[2], sc, bb0.z);
        r0.w = fmaf(acc[3], sc, bb0.w);
        r1.x = fmaf(acc[4], sc, bb1.x);
        r1.y = fmaf(acc[5], sc, bb1.y);
        r1.z = fmaf(acc[6], sc, bb1.z);
        r1.w = fmaf(acc[7], sc, bb1.w);
        if (RELU) {
            r0.x = fmaxf(r0.x, 0.f); r0.y = fmaxf(r0.y, 0.f);
            r0.z = fmaxf(r0.z, 0.f); r0.w = fmaxf(r0.w, 0.f);
            r1.x = fmaxf(r1.x, 0.f); r1.y = fmaxf(r1.y, 0.f);
            r1.z = fmaxf(r1.z, 0.f); r1.w = fmaxf(r1.w, 0.f);
        }
        float4* orow = ((float4*)(out + (size_t)w * 128)) + sub * 2;
        orow[0] = r0;
        orow[1] = r1;
    }
}

// ---------------- final aggregation over fp32 P (40 dims) ----------------
__global__ void __launch_bounds__(256)
k_agg40(const float* __restrict__ b, float* __restrict__ out, int n) {
    int t = blockIdx.x * blockDim.x + threadIdx.x;
    if (t >= n * 10) return;
    int node = t / 10;
    int g    = t - node * 10;

    int beg = g_rowstart[node];
    int end = g_rowstart[node + 1];

    float4 acc = make_float4(0.f, 0.f, 0.f, 0.f);
    const float4* P4 = (const float4*)g_P;
    int e = beg;
    for (; e + 2 <= end; e += 2) {
        int s0 = g_esrc[e];
        int s1 = g_esrc[e + 1];
        float4 v0 = P4[(size_t)s0 * 10 + g];
        float4 v1 = P4[(size_t)s1 * 10 + g];
        acc.x += v0.x; acc.y += v0.y; acc.z += v0.z; acc.w += v0.w;
        acc.x += v1.x; acc.y += v1.y; acc.z += v1.z; acc.w += v1.w;
    }
    if (e < end) {
        int s = g_esrc[e];
        float4 v = P4[(size_t)s * 10 + g];
        acc.x += v.x; acc.y += v.y; acc.z += v.z; acc.w += v.w;
    }

    float sc = rsqrtf(fmaxf((float)g_indeg[node], 1.f));
    float4 bb = ((const float4*)b)[g];
    float4 r;
    r.x = fmaf(acc.x, sc, bb.x);
    r.y = fmaf(acc.y, sc, bb.y);
    r.z = fmaf(acc.z, sc, bb.z);
    r.w = fmaf(acc.w, sc, bb.w);
    ((float4*)(out + (size_t)node * 40))[g] = r;
}

// ---------------- launch ----------------
extern "C" void kernel_launch(void* const* d_in, const int* in_sizes, int n_in,
                              void* d_out, int out_size) {
    const float* feat = (const float*)d_in[0];
    const float* W1   = (const float*)d_in[1];
    const float* b1   = (const float*)d_in[2];
    const float* W2   = (const float*)d_in[3];
    const float* b2   = (const float*)d_in[4];
    const float* W3   = (const float*)d_in[5];
    const float* b3   = (const float*)d_in[6];
    const int*   src  = (const int*)d_in[7];
    const int*   dst  = (const int*)d_in[8];

    const int N  = in_sizes[0] / 128;
    const int nE = in_sizes[7];
    float* out = (float*)d_out;

    __half* P16 = nullptr;
    float *P = nullptr, *H = nullptr;
    void *odeg = nullptr, *ideg = nullptr;
    cudaGetSymbolAddress((void**)&P16, g_P16);
    cudaGetSymbolAddress((void**)&P, g_P);
    cudaGetSymbolAddress((void**)&H, g_H);
    cudaGetSymbolAddress(&odeg, g_outdeg);
    cudaGetSymbolAddress(&ideg, g_indeg);

    const int SMEM_H16 = (128 * SXH + 128 * SWH) * 2;  // 71680 B
    const int SMEM_H40 = (128 * SXH + 40 * SWH) * 2;   // 47744 B
    cudaFuncSetAttribute(k_gemm_h16, cudaFuncAttributeMaxDynamicSharedMemorySize, SMEM_H16);
    cudaFuncSetAttribute(k_gemm_h16_40, cudaFuncAttributeMaxDynamicSharedMemorySize, SMEM_H40);

    const int T = 256;
    const int gemmBlocks = (N + 127) / 128;
    const int scanBlocks = (N + 255) / 256;
    const int aggBlocks  = (N * 32 + T - 1) / T;
    const int eBlocks    = (nE + T - 1) / T;

    cudaStream_t s1;
    cudaStreamCreateWithFlags(&s1, cudaStreamNonBlocking);
    cudaEvent_t e0, e2;
    cudaEventCreateWithFlags(&e0, cudaEventDisableTiming);
    cudaEventCreateWithFlags(&e2, cudaEventDisableTiming);

    // --- fork at t=0: side stream owns dst-side (indeg + CSR build) ---
    cudaEventRecord(e0, 0);
    cudaStreamWaitEvent(s1, e0, 0);

    cudaMemsetAsync(ideg, 0, (size_t)N * 4, s1);
    k_degree1<<<eBlocks, T, 0, s1>>>(dst, (int*)ideg, nE);
    k_scan1<<<scanBlocks, 256, 0, s1>>>(N);
    k_scan2<<<1, 256, 0, s1>>>(scanBlocks);
    k_scan3<<<scanBlocks, 256, 0, s1>>>(N);
    k_scatter<<<eBlocks, T, 0, s1>>>(src, dst, nE);
    cudaEventRecord(e2, s1);

    // --- main stream: src-side (outdeg) + GEMM1 ---
    cudaMemsetAsync(odeg, 0, (size_t)N * 4, 0);
    k_degree1<<<eBlocks, T>>>(src, (int*)odeg, nE);
    k_gemm_h16<<<gemmBlocks, T, SMEM_H16>>>(feat, W1, P16, N);

    // --- join ---
    cudaStreamWaitEvent(0, e2, 0);

    // layer 1 aggregation
    k_csr_agg128_h<true><<<aggBlocks, T>>>(b1, H, N);

    // layer 2
    k_gemm_h16<<<gemmBlocks, T, SMEM_H16>>>(H, W2, P16, N);
    k_csr_agg128_h<true><<<aggBlocks, T>>>(b2, H, N);

    // layer 3 (fp16 MMA, fp32 output)
    k_gemm_h16_40<<<gemmBlocks, T, SMEM_H40>>>(H, W3, P, N);
    k_agg40<<<(N * 10 + T - 1) / T, T>>>(b3, out, N);

    cudaStreamCaptureStatus cap = cudaStreamCaptureStatusNone;
    cudaStreamIsCapturing(s1, &cap);
    if (cap == cudaStreamCaptureStatusNone) {
        cudaEventDestroy(e0);
        cudaEventDestroy(e2);
        cudaStreamDestroy(s1);
    }
}

// round 17
// speedup vs baseline: 1.4306x; 1.0131x over previous
#include <cuda_runtime.h>
#include <cuda_fp16.h>
#include <cstdint>

#define NMAX 50000
#define NEMAX 1000000

// ---------------- scratch ----------------
__device__ __align__(16) __half g_P16[(size_t)NMAX * 128];  // GEMM outputs
__device__ __align__(16) __half g_H16[(size_t)NMAX * 128];  // agg outputs (hidden)
__device__ __align__(16) float  g_P  [(size_t)NMAX * 40 + 8];
__device__ __align__(16) int    g_outdeg[NMAX + 8];
__device__ __align__(16) int    g_indeg [NMAX + 8];
__device__ __align__(16) float  g_onorm [NMAX + 8];
__device__ int g_esrc[NEMAX];
__device__ int g_rowstart[NMAX + 8];
__device__ int g_cursor[NMAX + 8];
__device__ int g_scan[NMAX + 8];
__device__ int g_bsum[512];

// ---------------- helpers ----------------
__device__ __forceinline__ void mma_f16_k16(
    float& c0, float& c1, float& c2, float& c3,
    uint32_t a0, uint32_t a1, uint32_t a2, uint32_t a3,
    uint32_t b0, uint32_t b1)
{
    asm volatile(
        "mma.sync.aligned.m16n8k16.row.col.f32.f16.f16.f32 "
        "{%0,%1,%2,%3}, {%4,%5,%6,%7}, {%8,%9}, {%0,%1,%2,%3};"
        : "+f"(c0), "+f"(c1), "+f"(c2), "+f"(c3)
        : "r"(a0), "r"(a1), "r"(a2), "r"(a3), "r"(b0), "r"(b1));
}
// slot (in halfs, within a 16-k group) of k-pair p=(k>>1)&7: order (0,4,1,5,2,6,3,7)
__device__ __forceinline__ int pslot(int p) { return ((p & 3) * 2 + (p >> 2)) * 2; }

// ---------------- prologue ----------------
__global__ void k_deg_both(const int* __restrict__ src, const int* __restrict__ dst, int nE) {
    int i = blockIdx.x * blockDim.x + threadIdx.x;
    if (i < nE) {
        atomicAdd(&g_outdeg[src[i]], 1);
        atomicAdd(&g_indeg[dst[i]], 1);
    }
}
__global__ void k_norm(int n) {
    int i = blockIdx.x * blockDim.x + threadIdx.x;
    if (i < n) g_onorm[i] = rsqrtf(fmaxf((float)g_outdeg[i], 1.f));
}
__global__ void k_scan1(int n) {
    __shared__ int sm[256];
    int tid = threadIdx.x;
    int i = blockIdx.x * 256 + tid;
    int v = (i < n) ? g_indeg[i] : 0;
    sm[tid] = v;
    __syncthreads();
    for (int off = 1; off < 256; off <<= 1) {
        int t = 0;
        if (tid >= off) t = sm[tid - off];
        __syncthreads();
        if (tid >= off) sm[tid] += t;
        __syncthreads();
    }
    if (i < n) g_scan[i] = sm[tid];
    if (tid == 255) g_bsum[blockIdx.x] = sm[255];
}
__global__ void k_scan2(int nb) {
    __shared__ int sm[256];
    int tid = threadIdx.x;
    int v = (tid < nb) ? g_bsum[tid] : 0;
    sm[tid] = v;
    __syncthreads();
    for (int off = 1; off < 256; off <<= 1) {
        int t = 0;
        if (tid >= off) t = sm[tid - off];
        __syncthreads();
        if (tid >= off) sm[tid] += t;
        __syncthreads();
    }
    if (tid < nb) g_bsum[tid] = sm[tid] - v;
}
__global__ void k_scan3(int n) {
    int i = blockIdx.x * blockDim.x + threadIdx.x;
    if (i < n) {
        int incl = g_scan[i] + g_bsum[i >> 8];
        int start = incl - g_indeg[i];
        g_rowstart[i] = start;
        g_cursor[i]   = start;
        if (i == n - 1) g_rowstart[n] = incl;
    }
}
__global__ void k_scatter(const int* __restrict__ src, const int* __restrict__ dst, int nE) {
    int i = blockIdx.x * blockDim.x + threadIdx.x;
    if (i < nE) {
        int d = dst[i];
        int pos = atomicAdd(&g_cursor[d], 1);
        g_esrc[pos] = src[i];
    }
}

// ---------------- fp16 m16n8k16 GEMMs (no norm scaling; P = h(X) @ h(W)) ----
#define SXH 144
#define SWH 136

// stage Xs from fp32 input (layer 1: feat)
__device__ __forceinline__ void stage_xs_f32(
    __half* Xs, const float* __restrict__ X, int r0, int n, int tid)
{
    for (int q = tid; q < 128 * 32; q += 256) {
        int r = q >> 5, c4 = q & 31;
        int gr = r0 + r;
        float4 v = make_float4(0.f, 0.f, 0.f, 0.f);
        if (gr < n) v = ((const float4*)(X + (size_t)gr * 128))[c4];
        int k0 = c4 * 4;
        int base = k0 & ~15;
        int p0 = (k0 >> 1) & 7;
        __half* row = Xs + r * SXH + base;
        *(__half2*)(row + pslot(p0))     = __floats2half2_rn(v.x, v.y);
        *(__half2*)(row + pslot(p0 + 1)) = __floats2half2_rn(v.z, v.w);
    }
}

// stage Xs from fp16 input (layers 2,3: H16), pure interleaved copy
__device__ __forceinline__ void stage_xs_f16(
    __half* Xs, const __half* __restrict__ X, int r0, int n, int tid)
{
    for (int q = tid; q < 128 * 64; q += 256) {
        int r = q >> 6, pp = q & 63;      // pair index (k/2)
        int gr = r0 + r;
        int k0 = 2 * pp;
        uint32_t u = 0;
        if (gr < n) u = *(const uint32_t*)(X + (size_t)gr * 128 + k0);
        int slot = (k0 & ~15) + pslot((k0 >> 1) & 7);
        *(uint32_t*)(Xs + r * SXH + slot) = u;
    }
}

// mainloop + epilogue shared shape: warp = 16 rows, qr/qc quad coords.
__global__ void __launch_bounds__(256)
k_gemm1(const float* __restrict__ X, const float* __restrict__ W,
        __half* __restrict__ P, int n) {
    extern __shared__ __half smh[];
    __half* Xs = smh;
    __half* Wt = smh + 128 * SXH;

    const int tid  = threadIdx.x;
    const int lane = tid & 31;
    const int w    = tid >> 5;
    const int r0   = blockIdx.x * 128;
    const int qr   = lane >> 2;
    const int qc   = lane & 3;

    stage_xs_f32(Xs, X, r0, n, tid);
    for (int q = tid; q < 128 * 128; q += 256) {
        int kk = q >> 7, nn = q & 127;
        int s = (kk & ~15) + pslot((kk >> 1) & 7) + (kk & 1);
        Wt[nn * SWH + s] = __float2half_rn(W[kk * 128 + nn]);
    }
    __syncthreads();

    float acc[16][4];
#pragma unroll
    for (int t = 0; t < 16; ++t)
#pragma unroll
        for (int j = 0; j < 4; ++j) acc[t][j] = 0.f;

    const __half* xr1 = Xs + (16 * w + qr) * SXH + 4 * qc;
    const __half* xr2 = xr1 + 8 * SXH;
    const __half* br  = Wt + qr * SWH + 4 * qc;

#pragma unroll
    for (int kt = 0; kt < 8; ++kt) {
        int off = kt * 16;
        uint2 pA1 = *(const uint2*)(xr1 + off);
        uint2 pA2 = *(const uint2*)(xr2 + off);
#pragma unroll
        for (int ch = 0; ch < 2; ++ch) {
            uint2 bp[8];
#pragma unroll
            for (int j = 0; j < 8; ++j)
                bp[j] = *(const uint2*)(br + (ch * 8 + j) * 8 * SWH + off);
#pragma unroll
            for (int j = 0; j < 8; ++j) {
                int nt = ch * 8 + j;
                mma_f16_k16(acc[nt][0], acc[nt][1], acc[nt][2], acc[nt][3],
                            pA1.x, pA2.x, pA1.y, pA2.y, bp[j].x, bp[j].y);
            }
        }
    }

    int r1 = r0 + 16 * w + qr;
    int r2 = r1 + 8;
    __half* prow1 = P + (size_t)r1 * 128;
    __half* prow2 = P + (size_t)r2 * 128;
    bool ok1 = (r1 < n), ok2 = (r2 < n);
#pragma unroll
    for (int nt = 0; nt < 16; ++nt) {
        int col = nt * 8 + 2 * qc;
        if (ok1) *(__half2*)(prow1 + col) = __floats2half2_rn(acc[nt][0], acc[nt][1]);
        if (ok2) *(__half2*)(prow2 + col) = __floats2half2_rn(acc[nt][2], acc[nt][3]);
    }
}

__global__ void __launch_bounds__(256)
k_gemm_h(const __half* __restrict__ X, const float* __restrict__ W,
         __half* __restrict__ P, int n) {
    extern __shared__ __half smh[];
    __half* Xs = smh;
    __half* Wt = smh + 128 * SXH;

    const int tid  = threadIdx.x;
    const int lane = tid & 31;
    const int w    = tid >> 5;
    const int r0   = blockIdx.x * 128;
    const int qr   = lane >> 2;
    const int qc   = lane & 3;

    stage_xs_f16(Xs, X, r0, n, tid);
    for (int q = tid; q < 128 * 128; q += 256) {
        int kk = q >> 7, nn = q & 127;
        int s = (kk & ~15) + pslot((kk >> 1) & 7) + (kk & 1);
        Wt[nn * SWH + s] = __float2half_rn(W[kk * 128 + nn]);
    }
    __syncthreads();

    float acc[16][4];
#pragma unroll
    for (int t = 0; t < 16; ++t)
#pragma unroll
        for (int j = 0; j < 4; ++j) acc[t][j] = 0.f;

    const __half* xr1 = Xs + (16 * w + qr) * SXH + 4 * qc;
    const __half* xr2 = xr1 + 8 * SXH;
    const __half* br  = Wt + qr * SWH + 4 * qc;

#pragma unroll
    for (int kt = 0; kt < 8; ++kt) {
        int off = kt * 16;
        uint2 pA1 = *(const uint2*)(xr1 + off);
        uint2 pA2 = *(const uint2*)(xr2 + off);
#pragma unroll
        for (int ch = 0; ch < 2; ++ch) {
            uint2 bp[8];
#pragma unroll
            for (int j = 0; j < 8; ++j)
                bp[j] = *(const uint2*)(br + (ch * 8 + j) * 8 * SWH + off);
#pragma unroll
            for (int j = 0; j < 8; ++j) {
                int nt = ch * 8 + j;
                mma_f16_k16(acc[nt][0], acc[nt][1], acc[nt][2], acc[nt][3],
                            pA1.x, pA2.x, pA1.y, pA2.y, bp[j].x, bp[j].y);
            }
        }
    }

    int r1 = r0 + 16 * w + qr;
    int r2 = r1 + 8;
    __half* prow1 = P + (size_t)r1 * 128;
    __half* prow2 = P + (size_t)r2 * 128;
    bool ok1 = (r1 < n), ok2 = (r2 < n);
#pragma unroll
    for (int nt = 0; nt < 16; ++nt) {
        int col = nt * 8 + 2 * qc;
        if (ok1) *(__half2*)(prow1 + col) = __floats2half2_rn(acc[nt][0], acc[nt][1]);
        if (ok2) *(__half2*)(prow2 + col) = __floats2half2_rn(acc[nt][2], acc[nt][3]);
    }
}

// layer 3: 40 cols, fp16 input, fp32 output
__global__ void __launch_bounds__(256)
k_gemm_h40(const __half* __restrict__ X, const float* __restrict__ W,
           float* __restrict__ P, int n) {
    extern __shared__ __half smh[];
    __half* Xs = smh;
    __half* Wt = smh + 128 * SXH;

    const int tid  = threadIdx.x;
    const int lane = tid & 31;
    const int w    = tid >> 5;
    const int r0   = blockIdx.x * 128;
    const int qr   = lane >> 2;
    const int qc   = lane & 3;

    stage_xs_f16(Xs, X, r0, n, tid);
    for (int q = tid; q < 128 * 40; q += 256) {
        int kk = q / 40, nn = q % 40;
        int s = (kk & ~15) + pslot((kk >> 1) & 7) + (kk & 1);
        Wt[nn * SWH + s] = __float2half_rn(W[kk * 40 + nn]);
    }
    __syncthreads();

    float acc[5][4];
#pragma unroll
    for (int t = 0; t < 5; ++t)
#pragma unroll
        for (int j = 0; j < 4; ++j) acc[t][j] = 0.f;

    const __half* xr1 = Xs + (16 * w + qr) * SXH + 4 * qc;
    const __half* xr2 = xr1 + 8 * SXH;
    const __half* br  = Wt + qr * SWH + 4 * qc;

#pragma unroll
    for (int kt = 0; kt < 8; ++kt) {
        int off = kt * 16;
        uint2 pA1 = *(const uint2*)(xr1 + off);
        uint2 pA2 = *(const uint2*)(xr2 + off);
        uint2 bp[5];
#pragma unroll
        for (int j = 0; j < 5; ++j)
            bp[j] = *(const uint2*)(br + j * 8 * SWH + off);
#pragma unroll
        for (int j = 0; j < 5; ++j)
            mma_f16_k16(acc[j][0], acc[j][1], acc[j][2], acc[j][3],
                        pA1.x, pA2.x, pA1.y, pA2.y, bp[j].x, bp[j].y);
    }

    int r1 = r0 + 16 * w + qr;
    int r2 = r1 + 8;
    bool ok1 = (r1 < n), ok2 = (r2 < n);
#pragma unroll
    for (int nt = 0; nt < 5; ++nt) {
        int col = nt * 8 + 2 * qc;
        if (ok1) *(float2*)(P + (size_t)r1 * 40 + col) = make_float2(acc[nt][0], acc[nt][1]);
        if (ok2) *(float2*)(P + (size_t)r2 * 40 + col) = make_float2(acc[nt][2], acc[nt][3]);
    }
}

// ---------------- CSR aggregation: H16[d] = h(relu(inorm*Σ onorm[s]*P16[s] + b)) --
__global__ void __launch_bounds__(256)
k_csr_agg128(const float* __restrict__ b, __half* __restrict__ out, int n) {
    int w    = (blockIdx.x * blockDim.x + threadIdx.x) >> 5;
    if (w >= n) return;
    int lane = threadIdx.x & 31;
    int sub  = lane & 15;
    int grp  = lane >> 4;

    int beg = g_rowstart[w];
    int end = g_rowstart[w + 1];

    float acc[8];
#pragma unroll
    for (int j = 0; j < 8; ++j) acc[j] = 0.f;

    const uint4* P16 = (const uint4*)g_P16;

    for (int base = beg; base < end; base += 32) {
        int cnt = min(32, end - base);
        int myidx = 0;
        float myon = 0.f;
        if (lane < cnt) {
            myidx = g_esrc[base + lane];
            myon  = g_onorm[myidx];
        }
        int j = 0;
        for (; j + 4 <= cnt; j += 4) {
            int sA = __shfl_sync(0xffffffffu, myidx, j + grp);
            int sB = __shfl_sync(0xffffffffu, myidx, j + 2 + grp);
            float oA = __shfl_sync(0xffffffffu, myon, j + grp);
            float oB = __shfl_sync(0xffffffffu, myon, j + 2 + grp);
            uint4 vA = P16[(size_t)sA * 16 + sub];
            uint4 vB = P16[(size_t)sB * 16 + sub];
#pragma unroll
            for (int q = 0; q < 4; ++q) {
                uint32_t uA = (&vA.x)[q];
                uint32_t uB = (&vB.x)[q];
                float2 fA = __half22float2(*(__half2*)&uA);
                float2 fB = __half22float2(*(__half2*)&uB);
                acc[2 * q]     = fmaf(fA.x, oA, fmaf(fB.x, oB, acc[2 * q]));
                acc[2 * q + 1] = fmaf(fA.y, oA, fmaf(fB.y, oB, acc[2 * q + 1]));
            }
        }
        for (; j + 2 <= cnt; j += 2) {
            int s = __shfl_sync(0xffffffffu, myidx, j + grp);
            float o = __shfl_sync(0xffffffffu, myon, j + grp);
            uint4 v = P16[(size_t)s * 16 + sub];
#pragma unroll
            for (int q = 0; q < 4; ++q) {
                uint32_t u = (&v.x)[q];
                float2 f = __half22float2(*(__half2*)&u);
                acc[2 * q]     = fmaf(f.x, o, acc[2 * q]);
                acc[2 * q + 1] = fmaf(f.y, o, acc[2 * q + 1]);
            }
        }
        if (j < cnt) {
            int s = __shfl_sync(0xffffffffu, myidx, j);
            float o = __shfl_sync(0xffffffffu, myon, j);
            if (grp == 0) {
                uint4 v = P16[(size_t)s * 16 + sub];
#pragma unroll
                for (int q = 0; q < 4; ++q) {
                    uint32_t u = (&v.x)[q];
                    float2 f = __half22float2(*(__half2*)&u);
                    acc[2 * q]     = fmaf(f.x, o, acc[2 * q]);
                    acc[2 * q + 1] = fmaf(f.y, o, acc[2 * q + 1]);
                }
            }
        }
    }

#pragma unroll
    for (int q = 0; q < 8; ++q)
        acc[q] += __shfl_xor_sync(0xffffffffu, acc[q], 16);

    if (grp == 0) {
        float sc = rsqrtf(fmaxf((float)g_indeg[w], 1.f));
        const float4* b4 = ((const float4*)b) + sub * 2;
        float4 bb0 = b4[0];
        float4 bb1 = b4[1];
        float r0 = fmaxf(fmaf(acc[0], sc, bb0.x), 0.f);
        float r1 = fmaxf(fmaf(acc[1], sc, bb0.y), 0.f);
        float r2 = fmaxf(fmaf(acc[2], sc, bb0.z), 0.f);
        float r3 = fmaxf(fmaf(acc[3], sc, bb0.w), 0.f);
        float r4 = fmaxf(fmaf(acc[4], sc, bb1.x), 0.f);
        float r5 = fmaxf(fmaf(acc[5], sc, bb1.y), 0.f);
        float r6 = fmaxf(fmaf(acc[6], sc, bb1.z), 0.f);
        float r7 = fmaxf(fmaf(acc[7], sc, bb1.w), 0.f);
        __half2 h0 = __floats2half2_rn(r0, r1);
        __half2 h1 = __floats2half2_rn(r2, r3);
        __half2 h2 = __floats2half2_rn(r4, r5);
        __half2 h3 = __floats2half2_rn(r6, r7);
        uint4 u;
        u.x = *(uint32_t*)&h0; u.y = *(uint32_t*)&h1;
        u.z = *(uint32_t*)&h2; u.w = *(uint32_t*)&h3;
        *(uint4*)(out + (size_t)w * 128 + sub * 8) = u;
    }
}

// final aggregation over fp32 P40: out = inorm*Σ onorm[s]*P[s] + b
__global__ void __launch_bounds__(256)
k_agg40(const float* __restrict__ b, float* __restrict__ out, int n) {
    int t = blockIdx.x * blockDim.x + threadIdx.x;
    if (t >= n * 10) return;
    int node = t / 10;
    int g    = t - node * 10;

    int beg = g_rowstart[node];
    int end = g_rowstart[node + 1];

    float4 acc = make_float4(0.f, 0.f, 0.f, 0.f);
    const float4* P4 = (const float4*)g_P;
    for (int e = beg; e < end; ++e) {
        int s = g_esrc[e];
        float o = g_onorm[s];
        float4 v = P4[(size_t)s * 10 + g];
        acc.x = fmaf(v.x, o, acc.x);
        acc.y = fmaf(v.y, o, acc.y);
        acc.z = fmaf(v.z, o, acc.z);
        acc.w = fmaf(v.w, o, acc.w);
    }

    float sc = rsqrtf(fmaxf((float)g_indeg[node], 1.f));
    float4 bb = ((const float4*)b)[g];
    float4 r;
    r.x = fmaf(acc.x, sc, bb.x);
    r.y = fmaf(acc.y, sc, bb.y);
    r.z = fmaf(acc.z, sc, bb.z);
    r.w = fmaf(acc.w, sc, bb.w);
    ((float4*)(out + (size_t)node * 40))[g] = r;
}

// ---------------- launch ----------------
extern "C" void kernel_launch(void* const* d_in, const int* in_sizes, int n_in,
                              void* d_out, int out_size) {
    const float* feat = (const float*)d_in[0];
    const float* W1   = (const float*)d_in[1];
    const float* b1   = (const float*)d_in[2];
    const float* W2   = (const float*)d_in[3];
    const float* b2   = (const float*)d_in[4];
    const float* W3   = (const float*)d_in[5];
    const float* b3   = (const float*)d_in[6];
    const int*   src  = (const int*)d_in[7];
    const int*   dst  = (const int*)d_in[8];

    const int N  = in_sizes[0] / 128;
    const int nE = in_sizes[7];
    float* out = (float*)d_out;

    __half *P16 = nullptr, *H16 = nullptr;
    float* P = nullptr;
    void *odeg = nullptr, *ideg = nullptr;
    cudaGetSymbolAddress((void**)&P16, g_P16);
    cudaGetSymbolAddress((void**)&H16, g_H16);
    cudaGetSymbolAddress((void**)&P, g_P);
    cudaGetSymbolAddress(&odeg, g_outdeg);
    cudaGetSymbolAddress(&ideg, g_indeg);

    const int SMEM_H  = (128 * SXH + 128 * SWH) * 2;  // 71680 B
    const int SMEM_40 = (128 * SXH + 40 * SWH) * 2;   // 47744 B
    cudaFuncSetAttribute(k_gemm1,   cudaFuncAttributeMaxDynamicSharedMemorySize, SMEM_H);
    cudaFuncSetAttribute(k_gemm_h,  cudaFuncAttributeMaxDynamicSharedMemorySize, SMEM_H);
    cudaFuncSetAttribute(k_gemm_h40, cudaFuncAttributeMaxDynamicSharedMemorySize, SMEM_40);

    const int T = 256;
    const int gemmBlocks = (N + 127) / 128;
    const int scanBlocks = (N + 255) / 256;
    const int aggBlocks  = (N * 32 + T - 1) / T;
    const int eBlocks    = (nE + T - 1) / T;

    cudaStream_t s1;
    cudaStreamCreateWithFlags(&s1, cudaStreamNonBlocking);
    cudaEvent_t e0, e2;
    cudaEventCreateWithFlags(&e0, cudaEventDisableTiming);
    cudaEventCreateWithFlags(&e2, cudaEventDisableTiming);

    // --- fork at t=0: side stream owns the ENTIRE graph prologue ---
    cudaEventRecord(e0, 0);
    cudaStreamWaitEvent(s1, e0, 0);

    cudaMemsetAsync(odeg, 0, (size_t)N * 4, s1);
    cudaMemsetAsync(ideg, 0, (size_t)N * 4, s1);
    k_deg_both<<<eBlocks, T, 0, s1>>>(src, dst, nE);
    k_norm<<<(N + T - 1) / T, T, 0, s1>>>(N);
    k_scan1<<<scanBlocks, 256, 0, s1>>>(N);
    k_scan2<<<1, 256, 0, s1>>>(scanBlocks);
    k_scan3<<<scanBlocks, 256, 0, s1>>>(N);
    k_scatter<<<eBlocks, T, 0, s1>>>(src, dst, nE);
    cudaEventRecord(e2, s1);

    // --- main stream: GEMM1 at t=0 (no degree dependency) ---
    k_gemm1<<<gemmBlocks, T, SMEM_H>>>(feat, W1, P16, N);

    // --- join ---
    cudaStreamWaitEvent(0, e2, 0);

    // layer 1 aggregation -> H16
    k_csr_agg128<<<aggBlocks, T>>>(b1, H16, N);

    // layer 2
    k_gemm_h<<<gemmBlocks, T, SMEM_H>>>(H16, W2, P16, N);
    k_csr_agg128<<<aggBlocks, T>>>(b2, H16, N);

    // layer 3
    k_gemm_h40<<<gemmBlocks, T, SMEM_40>>>(H16, W3, P, N);
    k_agg40<<<(N * 10 + T - 1) / T, T>>>(b3, out, N);

    cudaStreamCaptureStatus cap = cudaStreamCaptureStatusNone;
    cudaStreamIsCapturing(s1, &cap);
    if (cap == cudaStreamCaptureStatusNone) {
        cudaEventDestroy(e0);
        cudaEventDestroy(e2);
        cudaStreamDestroy(s1);
    }
}